// round 1
// baseline (speedup 1.0000x reference)
#include <cuda_runtime.h>
#include <math.h>

#define BB   4
#define SS   2048
#define EE   1024
#define HH   16
#define DKK  64
#define MTOT (BB*SS)   // 8192

// Scratch (device globals; no allocation allowed)
__device__ float g_Q[(size_t)BB*HH*SS*DKK];
__device__ float g_K[(size_t)BB*HH*SS*DKK];
__device__ float g_V[(size_t)BB*HH*SS*DKK];
__device__ float g_A[(size_t)MTOT*EE];

// ---------------------------------------------------------------------------
// 128x128x16 register-blocked SGEMM, 256 threads, 8x8 microtile.
// ---------------------------------------------------------------------------

// QKV projection: Y = X @ W{Q,K,V}, written in [B,H,S,dk] layout.
__global__ __launch_bounds__(256) void qkv_gemm(
    const float* __restrict__ X,
    const float* __restrict__ WQ,
    const float* __restrict__ WK,
    const float* __restrict__ WV)
{
    __shared__ float As[16][132];   // A tile transposed: As[k][m]
    __shared__ float Bs[16][132];   // B tile natural:    Bs[k][n]

    const float* W  = (blockIdx.z == 0) ? WQ : ((blockIdx.z == 1) ? WK : WV);
    float*       out = (blockIdx.z == 0) ? g_Q : ((blockIdx.z == 1) ? g_K : g_V);

    const int tid = threadIdx.x;
    const int tx  = tid & 15;
    const int ty  = tid >> 4;
    const int m0  = blockIdx.y * 128;
    const int n0  = blockIdx.x * 128;

    float acc[8][8];
#pragma unroll
    for (int i = 0; i < 8; i++)
#pragma unroll
        for (int j = 0; j < 8; j++) acc[i][j] = 0.f;

    for (int k0 = 0; k0 < EE; k0 += 16) {
        // Load A tile (128 rows x 16 cols), store transposed.
#pragma unroll
        for (int f = tid; f < 512; f += 256) {
            int r  = f >> 2;
            int c4 = f & 3;
            float4 v = *(const float4*)(X + (size_t)(m0 + r) * EE + k0 + c4 * 4);
            As[c4 * 4 + 0][r] = v.x;
            As[c4 * 4 + 1][r] = v.y;
            As[c4 * 4 + 2][r] = v.z;
            As[c4 * 4 + 3][r] = v.w;
        }
        // Load B tile (16 rows x 128 cols), natural layout.
#pragma unroll
        for (int f = tid; f < 512; f += 256) {
            int r  = f >> 5;
            int c4 = f & 31;
            *(float4*)&Bs[r][c4 * 4] =
                *(const float4*)(W + (size_t)(k0 + r) * EE + n0 + c4 * 4);
        }
        __syncthreads();

#pragma unroll
        for (int k = 0; k < 16; k++) {
            float a[8], b[8];
            *(float4*)&a[0] = *(float4*)&As[k][ty * 8];
            *(float4*)&a[4] = *(float4*)&As[k][ty * 8 + 4];
            *(float4*)&b[0] = *(float4*)&Bs[k][tx * 8];
            *(float4*)&b[4] = *(float4*)&Bs[k][tx * 8 + 4];
#pragma unroll
            for (int i = 0; i < 8; i++)
#pragma unroll
                for (int j = 0; j < 8; j++)
                    acc[i][j] = fmaf(a[i], b[j], acc[i][j]);
        }
        __syncthreads();
    }

    // Write out in [B,H,S,dk] layout. n stays within one head per float4x2.
#pragma unroll
    for (int i = 0; i < 8; i++) {
        int m = m0 + ty * 8 + i;
        int b = m >> 11;           // /2048
        int s = m & (SS - 1);
        int n = n0 + tx * 8;
        int h = n >> 6;
        int d = n & 63;
        float* o = out + (((size_t)(b * HH + h) * SS + s) * DKK + d);
        *(float4*)(o)     = make_float4(acc[i][0], acc[i][1], acc[i][2], acc[i][3]);
        *(float4*)(o + 4) = make_float4(acc[i][4], acc[i][5], acc[i][6], acc[i][7]);
    }
}

// Output projection: out = g_A @ WO (plain row-major out).
__global__ __launch_bounds__(256) void out_gemm(
    const float* __restrict__ WO, float* __restrict__ Out)
{
    __shared__ float As[16][132];
    __shared__ float Bs[16][132];

    const int tid = threadIdx.x;
    const int tx  = tid & 15;
    const int ty  = tid >> 4;
    const int m0  = blockIdx.y * 128;
    const int n0  = blockIdx.x * 128;

    float acc[8][8];
#pragma unroll
    for (int i = 0; i < 8; i++)
#pragma unroll
        for (int j = 0; j < 8; j++) acc[i][j] = 0.f;

    for (int k0 = 0; k0 < EE; k0 += 16) {
#pragma unroll
        for (int f = tid; f < 512; f += 256) {
            int r  = f >> 2;
            int c4 = f & 3;
            float4 v = *(const float4*)(g_A + (size_t)(m0 + r) * EE + k0 + c4 * 4);
            As[c4 * 4 + 0][r] = v.x;
            As[c4 * 4 + 1][r] = v.y;
            As[c4 * 4 + 2][r] = v.z;
            As[c4 * 4 + 3][r] = v.w;
        }
#pragma unroll
        for (int f = tid; f < 512; f += 256) {
            int r  = f >> 5;
            int c4 = f & 31;
            *(float4*)&Bs[r][c4 * 4] =
                *(const float4*)(WO + (size_t)(k0 + r) * EE + n0 + c4 * 4);
        }
        __syncthreads();

#pragma unroll
        for (int k = 0; k < 16; k++) {
            float a[8], b[8];
            *(float4*)&a[0] = *(float4*)&As[k][ty * 8];
            *(float4*)&a[4] = *(float4*)&As[k][ty * 8 + 4];
            *(float4*)&b[0] = *(float4*)&Bs[k][tx * 8];
            *(float4*)&b[4] = *(float4*)&Bs[k][tx * 8 + 4];
#pragma unroll
            for (int i = 0; i < 8; i++)
#pragma unroll
                for (int j = 0; j < 8; j++)
                    acc[i][j] = fmaf(a[i], b[j], acc[i][j]);
        }
        __syncthreads();
    }

#pragma unroll
    for (int i = 0; i < 8; i++) {
        int m = m0 + ty * 8 + i;
        float* o = Out + (size_t)m * EE + n0 + tx * 8;
        *(float4*)(o)     = make_float4(acc[i][0], acc[i][1], acc[i][2], acc[i][3]);
        *(float4*)(o + 4) = make_float4(acc[i][4], acc[i][5], acc[i][6], acc[i][7]);
    }
}

// ---------------------------------------------------------------------------
// Causal flash attention, fp32. One CTA = 64 query rows of one (b,h).
// 256 threads as 16x16; each thread owns a 4(row) x 4(col) microtile.
// ---------------------------------------------------------------------------

#define ATTN_SMEM_FLOATS (64*68 + 64*68 + 64*64 + 64*64)
#define ATTN_SMEM_BYTES  (ATTN_SMEM_FLOATS * 4)

__global__ __launch_bounds__(256) void attn_kernel()
{
    extern __shared__ float sm[];
    float* Qt = sm;                       // [64][68]  Qt[d*68 + r]
    float* Kt = sm + 64 * 68;             // [64][68]  Kt[d*68 + t]
    float* Vs = sm + 2 * 64 * 68;         // [64][64]  Vs[t*64 + d]
    float* Ps = Vs + 64 * 64;             // [64][64]  Ps[r*64 + t]

    const int tid = threadIdx.x;
    const int tx  = tid & 15;
    const int ty  = tid >> 4;
    const int q0  = blockIdx.x * 64;
    const int h   = blockIdx.y;
    const int b   = blockIdx.z;
    const size_t base = ((size_t)(b * HH + h) * SS) * DKK;

    // Load Q tile (64 x 64), transposed into Qt[d][r].
#pragma unroll
    for (int f = tid; f < 1024; f += 256) {
        int r  = f >> 4;
        int c4 = f & 15;
        float4 v = *(const float4*)(g_Q + base + (size_t)(q0 + r) * DKK + c4 * 4);
        Qt[(c4 * 4 + 0) * 68 + r] = v.x;
        Qt[(c4 * 4 + 1) * 68 + r] = v.y;
        Qt[(c4 * 4 + 2) * 68 + r] = v.z;
        Qt[(c4 * 4 + 3) * 68 + r] = v.w;
    }

    float mi[4], li[4], acc[4][4];
#pragma unroll
    for (int i = 0; i < 4; i++) {
        mi[i] = -1e30f;
        li[i] = 0.f;
#pragma unroll
        for (int j = 0; j < 4; j++) acc[i][j] = 0.f;
    }

    for (int t0 = 0; t0 <= q0; t0 += 64) {
        __syncthreads();  // protects Qt (first iter) and Kt/Vs/Ps reuse

        // Load K (transposed) and V (natural) tiles.
#pragma unroll
        for (int f = tid; f < 1024; f += 256) {
            int r  = f >> 4;
            int c4 = f & 15;
            float4 kv = *(const float4*)(g_K + base + (size_t)(t0 + r) * DKK + c4 * 4);
            Kt[(c4 * 4 + 0) * 68 + r] = kv.x;
            Kt[(c4 * 4 + 1) * 68 + r] = kv.y;
            Kt[(c4 * 4 + 2) * 68 + r] = kv.z;
            Kt[(c4 * 4 + 3) * 68 + r] = kv.w;
            float4 vv = *(const float4*)(g_V + base + (size_t)(t0 + r) * DKK + c4 * 4);
            *(float4*)&Vs[r * 64 + c4 * 4] = vv;
        }
        __syncthreads();

        // S = Q K^T (4x4 per thread), over d=0..63.
        float s[4][4];
#pragma unroll
        for (int i = 0; i < 4; i++)
#pragma unroll
            for (int j = 0; j < 4; j++) s[i][j] = 0.f;

#pragma unroll
        for (int k = 0; k < 64; k++) {
            float4 a  = *(float4*)&Qt[k * 68 + ty * 4];   // broadcast within half-warp
            float4 bb = *(float4*)&Kt[k * 68 + tx * 4];
            s[0][0] = fmaf(a.x, bb.x, s[0][0]); s[0][1] = fmaf(a.x, bb.y, s[0][1]);
            s[0][2] = fmaf(a.x, bb.z, s[0][2]); s[0][3] = fmaf(a.x, bb.w, s[0][3]);
            s[1][0] = fmaf(a.y, bb.x, s[1][0]); s[1][1] = fmaf(a.y, bb.y, s[1][1]);
            s[1][2] = fmaf(a.y, bb.z, s[1][2]); s[1][3] = fmaf(a.y, bb.w, s[1][3]);
            s[2][0] = fmaf(a.z, bb.x, s[2][0]); s[2][1] = fmaf(a.z, bb.y, s[2][1]);
            s[2][2] = fmaf(a.z, bb.z, s[2][2]); s[2][3] = fmaf(a.z, bb.w, s[2][3]);
            s[3][0] = fmaf(a.w, bb.x, s[3][0]); s[3][1] = fmaf(a.w, bb.y, s[3][1]);
            s[3][2] = fmaf(a.w, bb.z, s[3][2]); s[3][3] = fmaf(a.w, bb.w, s[3][3]);
        }

        const bool diag = (t0 == q0);
#pragma unroll
        for (int i = 0; i < 4; i++)
#pragma unroll
            for (int j = 0; j < 4; j++) {
                s[i][j] *= 0.125f;   // 1/sqrt(64)
                if (diag && (tx * 4 + j > ty * 4 + i)) s[i][j] = -1e30f;
            }

        // Online softmax update per row.
#pragma unroll
        for (int i = 0; i < 4; i++) {
            float rm = fmaxf(fmaxf(s[i][0], s[i][1]), fmaxf(s[i][2], s[i][3]));
            rm = fmaxf(rm, __shfl_xor_sync(0xffffffffu, rm, 1));
            rm = fmaxf(rm, __shfl_xor_sync(0xffffffffu, rm, 2));
            rm = fmaxf(rm, __shfl_xor_sync(0xffffffffu, rm, 4));
            rm = fmaxf(rm, __shfl_xor_sync(0xffffffffu, rm, 8));
            float mnew = fmaxf(mi[i], rm);
            float sc   = __expf(mi[i] - mnew);
            float p0 = __expf(s[i][0] - mnew);
            float p1 = __expf(s[i][1] - mnew);
            float p2 = __expf(s[i][2] - mnew);
            float p3 = __expf(s[i][3] - mnew);
            float rs = (p0 + p1) + (p2 + p3);
            rs += __shfl_xor_sync(0xffffffffu, rs, 1);
            rs += __shfl_xor_sync(0xffffffffu, rs, 2);
            rs += __shfl_xor_sync(0xffffffffu, rs, 4);
            rs += __shfl_xor_sync(0xffffffffu, rs, 8);
            li[i] = li[i] * sc + rs;
            mi[i] = mnew;
            acc[i][0] *= sc; acc[i][1] *= sc; acc[i][2] *= sc; acc[i][3] *= sc;
            *(float4*)&Ps[(ty * 4 + i) * 64 + tx * 4] = make_float4(p0, p1, p2, p3);
        }
        __syncthreads();

        // O += P @ V
#pragma unroll
        for (int t = 0; t < 64; t++) {
            float4 v4 = *(float4*)&Vs[t * 64 + tx * 4];
            float p0 = Ps[(ty * 4 + 0) * 64 + t];
            float p1 = Ps[(ty * 4 + 1) * 64 + t];
            float p2 = Ps[(ty * 4 + 2) * 64 + t];
            float p3 = Ps[(ty * 4 + 3) * 64 + t];
            acc[0][0] = fmaf(p0, v4.x, acc[0][0]); acc[0][1] = fmaf(p0, v4.y, acc[0][1]);
            acc[0][2] = fmaf(p0, v4.z, acc[0][2]); acc[0][3] = fmaf(p0, v4.w, acc[0][3]);
            acc[1][0] = fmaf(p1, v4.x, acc[1][0]); acc[1][1] = fmaf(p1, v4.y, acc[1][1]);
            acc[1][2] = fmaf(p1, v4.z, acc[1][2]); acc[1][3] = fmaf(p1, v4.w, acc[1][3]);
            acc[2][0] = fmaf(p2, v4.x, acc[2][0]); acc[2][1] = fmaf(p2, v4.y, acc[2][1]);
            acc[2][2] = fmaf(p2, v4.z, acc[2][2]); acc[2][3] = fmaf(p2, v4.w, acc[2][3]);
            acc[3][0] = fmaf(p3, v4.x, acc[3][0]); acc[3][1] = fmaf(p3, v4.y, acc[3][1]);
            acc[3][2] = fmaf(p3, v4.z, acc[3][2]); acc[3][3] = fmaf(p3, v4.w, acc[3][3]);
        }
    }

    // Epilogue: normalize and write to [B,S,E] scratch.
#pragma unroll
    for (int i = 0; i < 4; i++) {
        float inv = 1.0f / li[i];
        int srow = q0 + ty * 4 + i;
        float* o = g_A + ((size_t)b * SS + srow) * EE + h * DKK + tx * 4;
        *(float4*)o = make_float4(acc[i][0] * inv, acc[i][1] * inv,
                                  acc[i][2] * inv, acc[i][3] * inv);
    }
}

// ---------------------------------------------------------------------------

extern "C" void kernel_launch(void* const* d_in, const int* in_sizes, int n_in,
                              void* d_out, int out_size)
{
    const float* x  = (const float*)d_in[0];
    const float* WQ = (const float*)d_in[1];
    const float* WK = (const float*)d_in[2];
    const float* WV = (const float*)d_in[3];
    const float* WO = (const float*)d_in[4];
    float* out = (float*)d_out;

    (void)in_sizes; (void)n_in; (void)out_size;

    // 1) QKV projections into [B,H,S,dk] scratch.
    qkv_gemm<<<dim3(EE / 128, MTOT / 128, 3), 256>>>(x, WQ, WK, WV);

    // 2) Causal flash attention (needs >48KB dynamic smem).
    cudaFuncSetAttribute(attn_kernel,
                         cudaFuncAttributeMaxDynamicSharedMemorySize,
                         ATTN_SMEM_BYTES);
    attn_kernel<<<dim3(SS / 64, HH, BB), 256, ATTN_SMEM_BYTES>>>();

    // 3) Output projection.
    out_gemm<<<dim3(EE / 128, MTOT / 128), 256>>>(WO, out);
}

// round 3
// speedup vs baseline: 1.6706x; 1.6706x over previous
#include <cuda_runtime.h>
#include <cstdint>
#include <math.h>

#define BB   4
#define SS   2048
#define EE   1024
#define HH   16
#define DKK  64
#define MTOT (BB*SS)   // 8192

// Scratch (device globals; no allocation allowed)
__device__ float g_Q[(size_t)BB*HH*SS*DKK];
__device__ float g_K[(size_t)BB*HH*SS*DKK];
__device__ float g_V[(size_t)BB*HH*SS*DKK];
__device__ float g_A[(size_t)MTOT*EE];
__device__ float g_WT[(size_t)4*EE*EE];   // transposed + tf32-rounded weights

// ===========================================================================
// mma.sync tf32 helpers (portable PTX, legal at compute_103)
// ===========================================================================

__device__ __forceinline__ uint32_t f2tf(float v) {
    uint32_t u;
    asm("cvt.rna.tf32.f32 %0, %1;" : "=r"(u) : "f"(v));
    return u;
}

// D(16x8) += A(16x8) * B(8x8), tf32 inputs, fp32 accum.
__device__ __forceinline__ void mma_tf32(float* c, const uint32_t* a, const uint32_t* b) {
    asm volatile(
        "mma.sync.aligned.m16n8k8.row.col.f32.tf32.tf32.f32 "
        "{%0,%1,%2,%3}, {%4,%5,%6,%7}, {%8,%9}, {%0,%1,%2,%3};"
        : "+f"(c[0]), "+f"(c[1]), "+f"(c[2]), "+f"(c[3])
        : "r"(a[0]), "r"(a[1]), "r"(a[2]), "r"(a[3]), "r"(b[0]), "r"(b[1]));
}

// ===========================================================================
// Weight transpose + round-to-tf32 prepass: g_WT[w][n][k] = rna(W_w[k][n])
// ===========================================================================
__global__ __launch_bounds__(256) void wtrans_kernel(
    const float* __restrict__ WQ, const float* __restrict__ WK,
    const float* __restrict__ WV, const float* __restrict__ WO)
{
    __shared__ float t[32][33];
    const int w = blockIdx.z;
    const float* W = (w == 0) ? WQ : (w == 1) ? WK : (w == 2) ? WV : WO;
    float* O = g_WT + (size_t)w * EE * EE;
    const int n0 = blockIdx.x * 32;
    const int k0 = blockIdx.y * 32;
    const int tx = threadIdx.x, ty = threadIdx.y;

#pragma unroll
    for (int i = ty; i < 32; i += 8)
        t[i][tx] = W[(size_t)(k0 + i) * EE + n0 + tx];
    __syncthreads();
#pragma unroll
    for (int i = ty; i < 32; i += 8) {
        float v = t[tx][i];  // = W[k0+tx][n0+i]
        O[(size_t)(n0 + i) * EE + k0 + tx] = __uint_as_float(f2tf(v));
    }
}

// ===========================================================================
// tf32 mma.sync GEMM: 128x128 tile, K=1024 in 32-wide chunks, 256 threads
// (8 warps, each 32m x 64n), register-prefetch double buffering.
// SMEM: 2 buffers x (A[128][36] + B[128][36]) floats = 73728 bytes dynamic.
// A rows stride 36 -> all fragment LDS patterns bank-conflict-free.
// MODE 0: A = X, B = W{Q,K,V} (blockIdx.z), out = g_{Q,K,V} in [B,H,S,dk].
// MODE 1: A = g_A, B = WO, out = d_out [M,E].
// ===========================================================================
#define GEMM_SMEM_FLOATS (2 * 2 * 128 * 36)
#define GEMM_SMEM_BYTES  (GEMM_SMEM_FLOATS * 4)   // 73728

template <int MODE>
__global__ __launch_bounds__(256) void gemm_tc(
    const float* __restrict__ Ain, float* __restrict__ OutP)
{
    extern __shared__ float smf[];
    const int tid  = threadIdx.x;
    const int lane = tid & 31;
    const int w    = tid >> 5;
    const int g    = lane >> 2;
    const int tg   = lane & 3;
    const int wm   = w & 3;    // 4 warps along m (32 rows each)
    const int wn   = w >> 2;   // 2 warps along n (64 cols each)
    const int m0   = blockIdx.y * 128;
    const int n0   = blockIdx.x * 128;

    const float* Ag = MODE ? g_A : Ain;
    const float* Bt = g_WT + (size_t)(MODE ? 3 : blockIdx.z) * EE * EE;
    float* outp;
    if (MODE) outp = OutP;
    else outp = (blockIdx.z == 0) ? g_Q : (blockIdx.z == 1) ? g_K : g_V;

    // Per-thread staging indices: 4 float4 for A, 4 for B per 128x32 chunk.
    const int srow = tid >> 3;        // 0..31 (+32*i)
    const int sc4  = tid & 7;         // 0..7 -> col = sc4*4

    float c[2][8][4];
#pragma unroll
    for (int mt = 0; mt < 2; mt++)
#pragma unroll
        for (int nt = 0; nt < 8; nt++)
#pragma unroll
            for (int i = 0; i < 4; i++) c[mt][nt][i] = 0.f;

    float4 ra[4], rb[4];

    // Prefetch chunk 0.
#pragma unroll
    for (int i = 0; i < 4; i++) {
        int r = srow + i * 32;
        ra[i] = *(const float4*)(Ag + (size_t)(m0 + r) * EE + sc4 * 4);
        rb[i] = *(const float4*)(Bt + (size_t)(n0 + r) * EE + sc4 * 4);
    }
    // Store chunk 0 into buffer 0 (A rounded to tf32, B pre-rounded).
    {
        float* As = smf;
        float* Bs = smf + 128 * 36;
#pragma unroll
        for (int i = 0; i < 4; i++) {
            int r = srow + i * 32;
            float* a = As + r * 36 + sc4 * 4;
            a[0] = __uint_as_float(f2tf(ra[i].x));
            a[1] = __uint_as_float(f2tf(ra[i].y));
            a[2] = __uint_as_float(f2tf(ra[i].z));
            a[3] = __uint_as_float(f2tf(ra[i].w));
            *(float4*)(Bs + r * 36 + sc4 * 4) = rb[i];
        }
    }
    __syncthreads();

    for (int j = 0; j < 32; j++) {
        // Prefetch chunk j+1 (global loads overlap the compute below).
        if (j < 31) {
            const int kg = (j + 1) * 32;
#pragma unroll
            for (int i = 0; i < 4; i++) {
                int r = srow + i * 32;
                ra[i] = *(const float4*)(Ag + (size_t)(m0 + r) * EE + kg + sc4 * 4);
                rb[i] = *(const float4*)(Bt + (size_t)(n0 + r) * EE + kg + sc4 * 4);
            }
        }

        // Compute chunk j from buffer j&1.
        const float* As = smf + (j & 1) * (2 * 128 * 36);
        const float* Bs = As + 128 * 36;
#pragma unroll
        for (int ks = 0; ks < 4; ks++) {
            const int k0 = ks * 8;
            uint32_t a[2][4], b[8][2];
#pragma unroll
            for (int mt = 0; mt < 2; mt++) {
                int r0 = wm * 32 + mt * 16 + g;
                a[mt][0] = __float_as_uint(As[(r0    ) * 36 + k0 + tg]);
                a[mt][1] = __float_as_uint(As[(r0 + 8) * 36 + k0 + tg]);
                a[mt][2] = __float_as_uint(As[(r0    ) * 36 + k0 + tg + 4]);
                a[mt][3] = __float_as_uint(As[(r0 + 8) * 36 + k0 + tg + 4]);
            }
#pragma unroll
            for (int nt = 0; nt < 8; nt++) {
                int n = wn * 64 + nt * 8 + g;
                b[nt][0] = __float_as_uint(Bs[n * 36 + k0 + tg]);
                b[nt][1] = __float_as_uint(Bs[n * 36 + k0 + tg + 4]);
            }
#pragma unroll
            for (int mt = 0; mt < 2; mt++)
#pragma unroll
                for (int nt = 0; nt < 8; nt++)
                    mma_tf32(c[mt][nt], a[mt], b[nt]);
        }

        // Stage chunk j+1 into the other buffer (free since iter j-1).
        if (j < 31) {
            float* Ad = smf + ((j + 1) & 1) * (2 * 128 * 36);
            float* Bd = Ad + 128 * 36;
#pragma unroll
            for (int i = 0; i < 4; i++) {
                int r = srow + i * 32;
                float* a = Ad + r * 36 + sc4 * 4;
                a[0] = __uint_as_float(f2tf(ra[i].x));
                a[1] = __uint_as_float(f2tf(ra[i].y));
                a[2] = __uint_as_float(f2tf(ra[i].z));
                a[3] = __uint_as_float(f2tf(ra[i].w));
                *(float4*)(Bd + r * 36 + sc4 * 4) = rb[i];
            }
        }
        __syncthreads();
    }

    // Epilogue: c[mt][nt] -> (rows g, g+8 of 16-tile; cols 2tg, 2tg+1 of 8-tile)
#pragma unroll
    for (int mt = 0; mt < 2; mt++) {
#pragma unroll
        for (int nt = 0; nt < 8; nt++) {
            int row = m0 + wm * 32 + mt * 16 + g;
            int col = n0 + wn * 64 + nt * 8 + 2 * tg;
            if (MODE) {
                float* o0 = outp + (size_t)row * EE + col;
                float* o1 = outp + (size_t)(row + 8) * EE + col;
                *(float2*)o0 = make_float2(c[mt][nt][0], c[mt][nt][1]);
                *(float2*)o1 = make_float2(c[mt][nt][2], c[mt][nt][3]);
            } else {
                int bidx = row >> 11;
                int s    = row & (SS - 1);
                int h    = col >> 6;
                int d    = col & 63;
                float* o0 = outp + (((size_t)(bidx * HH + h) * SS + s    ) * DKK + d);
                float* o1 = outp + (((size_t)(bidx * HH + h) * SS + s + 8) * DKK + d);
                *(float2*)o0 = make_float2(c[mt][nt][0], c[mt][nt][1]);
                *(float2*)o1 = make_float2(c[mt][nt][2], c[mt][nt][3]);
            }
        }
    }
}

// ===========================================================================
// Causal flash attention, fp32 SIMT (unchanged — known good).
// ===========================================================================

#define ATTN_SMEM_FLOATS (64*68 + 64*68 + 64*64 + 64*64)
#define ATTN_SMEM_BYTES  (ATTN_SMEM_FLOATS * 4)

__global__ __launch_bounds__(256) void attn_kernel()
{
    extern __shared__ float sm[];
    float* Qt = sm;
    float* Kt = sm + 64 * 68;
    float* Vs = sm + 2 * 64 * 68;
    float* Ps = Vs + 64 * 64;

    const int tid = threadIdx.x;
    const int tx  = tid & 15;
    const int ty  = tid >> 4;
    const int q0  = blockIdx.x * 64;
    const int h   = blockIdx.y;
    const int b   = blockIdx.z;
    const size_t base = ((size_t)(b * HH + h) * SS) * DKK;

#pragma unroll
    for (int f = tid; f < 1024; f += 256) {
        int r  = f >> 4;
        int c4 = f & 15;
        float4 v = *(const float4*)(g_Q + base + (size_t)(q0 + r) * DKK + c4 * 4);
        Qt[(c4 * 4 + 0) * 68 + r] = v.x;
        Qt[(c4 * 4 + 1) * 68 + r] = v.y;
        Qt[(c4 * 4 + 2) * 68 + r] = v.z;
        Qt[(c4 * 4 + 3) * 68 + r] = v.w;
    }

    float mi[4], li[4], acc[4][4];
#pragma unroll
    for (int i = 0; i < 4; i++) {
        mi[i] = -1e30f;
        li[i] = 0.f;
#pragma unroll
        for (int j = 0; j < 4; j++) acc[i][j] = 0.f;
    }

    for (int t0 = 0; t0 <= q0; t0 += 64) {
        __syncthreads();

#pragma unroll
        for (int f = tid; f < 1024; f += 256) {
            int r  = f >> 4;
            int c4 = f & 15;
            float4 kv = *(const float4*)(g_K + base + (size_t)(t0 + r) * DKK + c4 * 4);
            Kt[(c4 * 4 + 0) * 68 + r] = kv.x;
            Kt[(c4 * 4 + 1) * 68 + r] = kv.y;
            Kt[(c4 * 4 + 2) * 68 + r] = kv.z;
            Kt[(c4 * 4 + 3) * 68 + r] = kv.w;
            float4 vv = *(const float4*)(g_V + base + (size_t)(t0 + r) * DKK + c4 * 4);
            *(float4*)&Vs[r * 64 + c4 * 4] = vv;
        }
        __syncthreads();

        float s[4][4];
#pragma unroll
        for (int i = 0; i < 4; i++)
#pragma unroll
            for (int j = 0; j < 4; j++) s[i][j] = 0.f;

#pragma unroll
        for (int k = 0; k < 64; k++) {
            float4 a  = *(float4*)&Qt[k * 68 + ty * 4];
            float4 bb = *(float4*)&Kt[k * 68 + tx * 4];
            s[0][0] = fmaf(a.x, bb.x, s[0][0]); s[0][1] = fmaf(a.x, bb.y, s[0][1]);
            s[0][2] = fmaf(a.x, bb.z, s[0][2]); s[0][3] = fmaf(a.x, bb.w, s[0][3]);
            s[1][0] = fmaf(a.y, bb.x, s[1][0]); s[1][1] = fmaf(a.y, bb.y, s[1][1]);
            s[1][2] = fmaf(a.y, bb.z, s[1][2]); s[1][3] = fmaf(a.y, bb.w, s[1][3]);
            s[2][0] = fmaf(a.z, bb.x, s[2][0]); s[2][1] = fmaf(a.z, bb.y, s[2][1]);
            s[2][2] = fmaf(a.z, bb.z, s[2][2]); s[2][3] = fmaf(a.z, bb.w, s[2][3]);
            s[3][0] = fmaf(a.w, bb.x, s[3][0]); s[3][1] = fmaf(a.w, bb.y, s[3][1]);
            s[3][2] = fmaf(a.w, bb.z, s[3][2]); s[3][3] = fmaf(a.w, bb.w, s[3][3]);
        }

        const bool diag = (t0 == q0);
#pragma unroll
        for (int i = 0; i < 4; i++)
#pragma unroll
            for (int j = 0; j < 4; j++) {
                s[i][j] *= 0.125f;
                if (diag && (tx * 4 + j > ty * 4 + i)) s[i][j] = -1e30f;
            }

#pragma unroll
        for (int i = 0; i < 4; i++) {
            float rm = fmaxf(fmaxf(s[i][0], s[i][1]), fmaxf(s[i][2], s[i][3]));
            rm = fmaxf(rm, __shfl_xor_sync(0xffffffffu, rm, 1));
            rm = fmaxf(rm, __shfl_xor_sync(0xffffffffu, rm, 2));
            rm = fmaxf(rm, __shfl_xor_sync(0xffffffffu, rm, 4));
            rm = fmaxf(rm, __shfl_xor_sync(0xffffffffu, rm, 8));
            float mnew = fmaxf(mi[i], rm);
            float sc   = __expf(mi[i] - mnew);
            float p0 = __expf(s[i][0] - mnew);
            float p1 = __expf(s[i][1] - mnew);
            float p2 = __expf(s[i][2] - mnew);
            float p3 = __expf(s[i][3] - mnew);
            float rs = (p0 + p1) + (p2 + p3);
            rs += __shfl_xor_sync(0xffffffffu, rs, 1);
            rs += __shfl_xor_sync(0xffffffffu, rs, 2);
            rs += __shfl_xor_sync(0xffffffffu, rs, 4);
            rs += __shfl_xor_sync(0xffffffffu, rs, 8);
            li[i] = li[i] * sc + rs;
            mi[i] = mnew;
            acc[i][0] *= sc; acc[i][1] *= sc; acc[i][2] *= sc; acc[i][3] *= sc;
            *(float4*)&Ps[(ty * 4 + i) * 64 + tx * 4] = make_float4(p0, p1, p2, p3);
        }
        __syncthreads();

#pragma unroll
        for (int t = 0; t < 64; t++) {
            float4 v4 = *(float4*)&Vs[t * 64 + tx * 4];
            float p0 = Ps[(ty * 4 + 0) * 64 + t];
            float p1 = Ps[(ty * 4 + 1) * 64 + t];
            float p2 = Ps[(ty * 4 + 2) * 64 + t];
            float p3 = Ps[(ty * 4 + 3) * 64 + t];
            acc[0][0] = fmaf(p0, v4.x, acc[0][0]); acc[0][1] = fmaf(p0, v4.y, acc[0][1]);
            acc[0][2] = fmaf(p0, v4.z, acc[0][2]); acc[0][3] = fmaf(p0, v4.w, acc[0][3]);
            acc[1][0] = fmaf(p1, v4.x, acc[1][0]); acc[1][1] = fmaf(p1, v4.y, acc[1][1]);
            acc[1][2] = fmaf(p1, v4.z, acc[1][2]); acc[1][3] = fmaf(p1, v4.w, acc[1][3]);
            acc[2][0] = fmaf(p2, v4.x, acc[2][0]); acc[2][1] = fmaf(p2, v4.y, acc[2][1]);
            acc[2][2] = fmaf(p2, v4.z, acc[2][2]); acc[2][3] = fmaf(p2, v4.w, acc[2][3]);
            acc[3][0] = fmaf(p3, v4.x, acc[3][0]); acc[3][1] = fmaf(p3, v4.y, acc[3][1]);
            acc[3][2] = fmaf(p3, v4.z, acc[3][2]); acc[3][3] = fmaf(p3, v4.w, acc[3][3]);
        }
    }

#pragma unroll
    for (int i = 0; i < 4; i++) {
        float inv = 1.0f / li[i];
        int srow = q0 + ty * 4 + i;
        float* o = g_A + ((size_t)b * SS + srow) * EE + h * DKK + tx * 4;
        *(float4*)o = make_float4(acc[i][0] * inv, acc[i][1] * inv,
                                  acc[i][2] * inv, acc[i][3] * inv);
    }
}

// ===========================================================================

extern "C" void kernel_launch(void* const* d_in, const int* in_sizes, int n_in,
                              void* d_out, int out_size)
{
    const float* x  = (const float*)d_in[0];
    const float* WQ = (const float*)d_in[1];
    const float* WK = (const float*)d_in[2];
    const float* WV = (const float*)d_in[3];
    const float* WO = (const float*)d_in[4];
    float* out = (float*)d_out;

    (void)in_sizes; (void)n_in; (void)out_size;

    // 0) Transpose + tf32-round weights into scratch.
    wtrans_kernel<<<dim3(EE / 32, EE / 32, 4), dim3(32, 8)>>>(WQ, WK, WV, WO);

    // 1) QKV projections (mma.sync tf32) into [B,H,S,dk] scratch.
    cudaFuncSetAttribute(gemm_tc<0>,
                         cudaFuncAttributeMaxDynamicSharedMemorySize,
                         GEMM_SMEM_BYTES);
    gemm_tc<0><<<dim3(EE / 128, MTOT / 128, 3), 256, GEMM_SMEM_BYTES>>>(x, nullptr);

    // 2) Causal flash attention (fp32 SIMT).
    cudaFuncSetAttribute(attn_kernel,
                         cudaFuncAttributeMaxDynamicSharedMemorySize,
                         ATTN_SMEM_BYTES);
    attn_kernel<<<dim3(SS / 64, HH, BB), 256, ATTN_SMEM_BYTES>>>();

    // 3) Output projection (mma.sync tf32).
    cudaFuncSetAttribute(gemm_tc<1>,
                         cudaFuncAttributeMaxDynamicSharedMemorySize,
                         GEMM_SMEM_BYTES);
    gemm_tc<1><<<dim3(EE / 128, MTOT / 128), 256, GEMM_SMEM_BYTES>>>(nullptr, out);
}

// round 4
// speedup vs baseline: 2.7177x; 1.6267x over previous
#include <cuda_runtime.h>
#include <cstdint>
#include <math.h>

#define BB   4
#define SS   2048
#define EE   1024
#define HH   16
#define DKK  64
#define MTOT (BB*SS)   // 8192

// Scratch (device globals; no allocation allowed)
__device__ float g_Q[(size_t)BB*HH*SS*DKK];
__device__ float g_K[(size_t)BB*HH*SS*DKK];
__device__ float g_V[(size_t)BB*HH*SS*DKK];
__device__ float g_A[(size_t)MTOT*EE];
__device__ float g_WT[(size_t)4*EE*EE];   // transposed + tf32-rounded weights

// ===========================================================================
// mma.sync tf32 helpers (portable PTX, legal at compute_103)
// ===========================================================================

__device__ __forceinline__ uint32_t f2tf(float v) {
    uint32_t u;
    asm("cvt.rna.tf32.f32 %0, %1;" : "=r"(u) : "f"(v));
    return u;
}
__device__ __forceinline__ float f2tff(float v) {
    return __uint_as_float(f2tf(v));
}

// D(16x8) += A(16x8) * B(8x8), tf32 inputs, fp32 accum.
__device__ __forceinline__ void mma_tf32(float* c, const uint32_t* a, const uint32_t* b) {
    asm volatile(
        "mma.sync.aligned.m16n8k8.row.col.f32.tf32.tf32.f32 "
        "{%0,%1,%2,%3}, {%4,%5,%6,%7}, {%8,%9}, {%0,%1,%2,%3};"
        : "+f"(c[0]), "+f"(c[1]), "+f"(c[2]), "+f"(c[3])
        : "r"(a[0]), "r"(a[1]), "r"(a[2]), "r"(a[3]), "r"(b[0]), "r"(b[1]));
}

// ===========================================================================
// Weight transpose + round-to-tf32 prepass: g_WT[w][n][k] = rna(W_w[k][n])
// ===========================================================================
__global__ __launch_bounds__(256) void wtrans_kernel(
    const float* __restrict__ WQ, const float* __restrict__ WK,
    const float* __restrict__ WV, const float* __restrict__ WO)
{
    __shared__ float t[32][33];
    const int w = blockIdx.z;
    const float* W = (w == 0) ? WQ : (w == 1) ? WK : (w == 2) ? WV : WO;
    float* O = g_WT + (size_t)w * EE * EE;
    const int n0 = blockIdx.x * 32;
    const int k0 = blockIdx.y * 32;
    const int tx = threadIdx.x, ty = threadIdx.y;

#pragma unroll
    for (int i = ty; i < 32; i += 8)
        t[i][tx] = W[(size_t)(k0 + i) * EE + n0 + tx];
    __syncthreads();
#pragma unroll
    for (int i = ty; i < 32; i += 8) {
        float v = t[tx][i];  // = W[k0+tx][n0+i]
        O[(size_t)(n0 + i) * EE + k0 + tx] = f2tff(v);
    }
}

// ===========================================================================
// tf32 mma.sync GEMM (unchanged, validated): 128x128 tile, 256 threads.
// ===========================================================================
#define GEMM_SMEM_FLOATS (2 * 2 * 128 * 36)
#define GEMM_SMEM_BYTES  (GEMM_SMEM_FLOATS * 4)   // 73728

template <int MODE>
__global__ __launch_bounds__(256) void gemm_tc(
    const float* __restrict__ Ain, float* __restrict__ OutP)
{
    extern __shared__ float smf[];
    const int tid  = threadIdx.x;
    const int lane = tid & 31;
    const int w    = tid >> 5;
    const int g    = lane >> 2;
    const int tg   = lane & 3;
    const int wm   = w & 3;
    const int wn   = w >> 2;
    const int m0   = blockIdx.y * 128;
    const int n0   = blockIdx.x * 128;

    const float* Ag = MODE ? g_A : Ain;
    const float* Bt = g_WT + (size_t)(MODE ? 3 : blockIdx.z) * EE * EE;
    float* outp;
    if (MODE) outp = OutP;
    else outp = (blockIdx.z == 0) ? g_Q : (blockIdx.z == 1) ? g_K : g_V;

    const int srow = tid >> 3;
    const int sc4  = tid & 7;

    float c[2][8][4];
#pragma unroll
    for (int mt = 0; mt < 2; mt++)
#pragma unroll
        for (int nt = 0; nt < 8; nt++)
#pragma unroll
            for (int i = 0; i < 4; i++) c[mt][nt][i] = 0.f;

    float4 ra[4], rb[4];

#pragma unroll
    for (int i = 0; i < 4; i++) {
        int r = srow + i * 32;
        ra[i] = *(const float4*)(Ag + (size_t)(m0 + r) * EE + sc4 * 4);
        rb[i] = *(const float4*)(Bt + (size_t)(n0 + r) * EE + sc4 * 4);
    }
    {
        float* As = smf;
        float* Bs = smf + 128 * 36;
#pragma unroll
        for (int i = 0; i < 4; i++) {
            int r = srow + i * 32;
            float* a = As + r * 36 + sc4 * 4;
            a[0] = f2tff(ra[i].x); a[1] = f2tff(ra[i].y);
            a[2] = f2tff(ra[i].z); a[3] = f2tff(ra[i].w);
            *(float4*)(Bs + r * 36 + sc4 * 4) = rb[i];
        }
    }
    __syncthreads();

    for (int j = 0; j < 32; j++) {
        if (j < 31) {
            const int kg = (j + 1) * 32;
#pragma unroll
            for (int i = 0; i < 4; i++) {
                int r = srow + i * 32;
                ra[i] = *(const float4*)(Ag + (size_t)(m0 + r) * EE + kg + sc4 * 4);
                rb[i] = *(const float4*)(Bt + (size_t)(n0 + r) * EE + kg + sc4 * 4);
            }
        }

        const float* As = smf + (j & 1) * (2 * 128 * 36);
        const float* Bs = As + 128 * 36;
#pragma unroll
        for (int ks = 0; ks < 4; ks++) {
            const int k0 = ks * 8;
            uint32_t a[2][4], b[8][2];
#pragma unroll
            for (int mt = 0; mt < 2; mt++) {
                int r0 = wm * 32 + mt * 16 + g;
                a[mt][0] = __float_as_uint(As[(r0    ) * 36 + k0 + tg]);
                a[mt][1] = __float_as_uint(As[(r0 + 8) * 36 + k0 + tg]);
                a[mt][2] = __float_as_uint(As[(r0    ) * 36 + k0 + tg + 4]);
                a[mt][3] = __float_as_uint(As[(r0 + 8) * 36 + k0 + tg + 4]);
            }
#pragma unroll
            for (int nt = 0; nt < 8; nt++) {
                int n = wn * 64 + nt * 8 + g;
                b[nt][0] = __float_as_uint(Bs[n * 36 + k0 + tg]);
                b[nt][1] = __float_as_uint(Bs[n * 36 + k0 + tg + 4]);
            }
#pragma unroll
            for (int mt = 0; mt < 2; mt++)
#pragma unroll
                for (int nt = 0; nt < 8; nt++)
                    mma_tf32(c[mt][nt], a[mt], b[nt]);
        }

        if (j < 31) {
            float* Ad = smf + ((j + 1) & 1) * (2 * 128 * 36);
            float* Bd = Ad + 128 * 36;
#pragma unroll
            for (int i = 0; i < 4; i++) {
                int r = srow + i * 32;
                float* a = Ad + r * 36 + sc4 * 4;
                a[0] = f2tff(ra[i].x); a[1] = f2tff(ra[i].y);
                a[2] = f2tff(ra[i].z); a[3] = f2tff(ra[i].w);
                *(float4*)(Bd + r * 36 + sc4 * 4) = rb[i];
            }
        }
        __syncthreads();
    }

#pragma unroll
    for (int mt = 0; mt < 2; mt++) {
#pragma unroll
        for (int nt = 0; nt < 8; nt++) {
            int row = m0 + wm * 32 + mt * 16 + g;
            int col = n0 + wn * 64 + nt * 8 + 2 * tg;
            if (MODE) {
                float* o0 = outp + (size_t)row * EE + col;
                float* o1 = outp + (size_t)(row + 8) * EE + col;
                *(float2*)o0 = make_float2(c[mt][nt][0], c[mt][nt][1]);
                *(float2*)o1 = make_float2(c[mt][nt][2], c[mt][nt][3]);
            } else {
                int bidx = row >> 11;
                int s    = row & (SS - 1);
                int h    = col >> 6;
                int d    = col & 63;
                float* o0 = outp + (((size_t)(bidx * HH + h) * SS + s    ) * DKK + d);
                float* o1 = outp + (((size_t)(bidx * HH + h) * SS + s + 8) * DKK + d);
                *(float2*)o0 = make_float2(c[mt][nt][0], c[mt][nt][1]);
                *(float2*)o1 = make_float2(c[mt][nt][2], c[mt][nt][3]);
            }
        }
    }
}

// ===========================================================================
// Causal flash attention on tensor cores (mma.sync tf32).
// CTA = 128 query rows of one (b,h); 8 warps, each owns 16 q-rows x full
// 64-col kv chunk (warp-local softmax). KV chunk 64, double-buffered via
// register prefetch. K and V both consumed in NATURAL [t][d] layout.
// SMEM: Qs[128][68] + Ks[2][64][68] + Vs[2][64][68] + Ps[128][68] = 136KB.
// ===========================================================================
#define AST 68
#define ATTN_SMEM_FLOATS (128*AST + 2*64*AST + 2*64*AST + 128*AST)
#define ATTN_SMEM_BYTES  (ATTN_SMEM_FLOATS * 4)   // 139264

__global__ __launch_bounds__(256) void attn_tc()
{
    extern __shared__ float sm[];
    float* Qs = sm;                        // [128][68]
    float* Ks = sm + 128 * AST;            // [2][64][68]
    float* Vs = Ks + 2 * 64 * AST;         // [2][64][68]
    float* Ps = Vs + 2 * 64 * AST;         // [128][68]

    const int tid  = threadIdx.x;
    const int lane = tid & 31;
    const int w    = tid >> 5;
    const int g    = lane >> 2;
    const int tg   = lane & 3;

    const int qblk = gridDim.x - 1 - blockIdx.x;   // heavy CTAs first
    const int q0   = qblk * 128;
    const int h    = blockIdx.y;
    const int b    = blockIdx.z;
    const size_t base = ((size_t)(b * HH + h) * SS) * DKK;

    // Stage Q (tf32-rounded), 128x64.
#pragma unroll
    for (int i = 0; i < 8; i++) {
        int f = tid + i * 256;
        int r = f >> 4, c4 = f & 15;
        float4 v = *(const float4*)(g_Q + base + (size_t)(q0 + r) * DKK + c4 * 4);
        float* d = Qs + r * AST + c4 * 4;
        d[0] = f2tff(v.x); d[1] = f2tff(v.y); d[2] = f2tff(v.z); d[3] = f2tff(v.w);
    }

    float o[8][4];
#pragma unroll
    for (int nt = 0; nt < 8; nt++)
#pragma unroll
        for (int i = 0; i < 4; i++) o[nt][i] = 0.f;
    float m0 = -1e30f, m1 = -1e30f, l0 = 0.f, l1 = 0.f;

    const int nch   = 2 * qblk + 2;
    const int rbase = w * 16;                 // local q-row base for this warp
    const int grow0 = q0 + rbase + g;         // global row (thread's row pair: grow0, grow0+8)

    // Prefetch chunk 0 (K and V, 4 float4 each per thread).
    float4 rk[4], rv[4];
#pragma unroll
    for (int i = 0; i < 4; i++) {
        int f = tid + i * 256;
        int r = f >> 4, c4 = f & 15;
        rk[i] = *(const float4*)(g_K + base + (size_t)r * DKK + c4 * 4);
        rv[i] = *(const float4*)(g_V + base + (size_t)r * DKK + c4 * 4);
    }

    for (int j = 0; j < nch; j++) {
        float* Kd = Ks + (j & 1) * (64 * AST);
        float* Vd = Vs + (j & 1) * (64 * AST);
        // Store current chunk (rounded).
#pragma unroll
        for (int i = 0; i < 4; i++) {
            int f = tid + i * 256;
            int r = f >> 4, c4 = f & 15;
            float* kd = Kd + r * AST + c4 * 4;
            kd[0] = f2tff(rk[i].x); kd[1] = f2tff(rk[i].y);
            kd[2] = f2tff(rk[i].z); kd[3] = f2tff(rk[i].w);
            float* vd = Vd + r * AST + c4 * 4;
            vd[0] = f2tff(rv[i].x); vd[1] = f2tff(rv[i].y);
            vd[2] = f2tff(rv[i].z); vd[3] = f2tff(rv[i].w);
        }
        __syncthreads();

        // Prefetch next chunk (overlaps compute below).
        if (j + 1 < nch) {
            const int tn = (j + 1) * 64;
#pragma unroll
            for (int i = 0; i < 4; i++) {
                int f = tid + i * 256;
                int r = f >> 4, c4 = f & 15;
                rk[i] = *(const float4*)(g_K + base + (size_t)(tn + r) * DKK + c4 * 4);
                rv[i] = *(const float4*)(g_V + base + (size_t)(tn + r) * DKK + c4 * 4);
            }
        }

        const int t0 = j * 64;
        // Whole-warp skip: all 16 rows of this warp below the chunk -> masked out.
        if (t0 <= q0 + rbase + 15) {
            // ---- S = Q K^T (16x64 per warp) ----
            float s[8][4];
#pragma unroll
            for (int nt = 0; nt < 8; nt++)
#pragma unroll
                for (int i = 0; i < 4; i++) s[nt][i] = 0.f;

#pragma unroll
            for (int ks = 0; ks < 8; ks++) {
                uint32_t a[4];
                a[0] = __float_as_uint(Qs[(rbase + g    ) * AST + ks * 8 + tg]);
                a[1] = __float_as_uint(Qs[(rbase + g + 8) * AST + ks * 8 + tg]);
                a[2] = __float_as_uint(Qs[(rbase + g    ) * AST + ks * 8 + tg + 4]);
                a[3] = __float_as_uint(Qs[(rbase + g + 8) * AST + ks * 8 + tg + 4]);
#pragma unroll
                for (int nt = 0; nt < 8; nt++) {
                    uint32_t bf[2];
                    bf[0] = __float_as_uint(Kd[(nt * 8 + g) * AST + ks * 8 + tg]);
                    bf[1] = __float_as_uint(Kd[(nt * 8 + g) * AST + ks * 8 + tg + 4]);
                    mma_tf32(s[nt], a, bf);
                }
            }

            // ---- scale + causal mask ----
#pragma unroll
            for (int nt = 0; nt < 8; nt++) {
                int c0 = t0 + nt * 8 + 2 * tg;
                int c1 = c0 + 1;
                s[nt][0] = (c0 <= grow0    ) ? s[nt][0] * 0.125f : -1e30f;
                s[nt][1] = (c1 <= grow0    ) ? s[nt][1] * 0.125f : -1e30f;
                s[nt][2] = (c0 <= grow0 + 8) ? s[nt][2] * 0.125f : -1e30f;
                s[nt][3] = (c1 <= grow0 + 8) ? s[nt][3] * 0.125f : -1e30f;
            }

            // ---- online softmax (rows grow0 and grow0+8; reduce over tg lanes) ----
            float mx0 = -1e30f, mx1 = -1e30f;
#pragma unroll
            for (int nt = 0; nt < 8; nt++) {
                mx0 = fmaxf(mx0, fmaxf(s[nt][0], s[nt][1]));
                mx1 = fmaxf(mx1, fmaxf(s[nt][2], s[nt][3]));
            }
            mx0 = fmaxf(mx0, __shfl_xor_sync(0xffffffffu, mx0, 1));
            mx0 = fmaxf(mx0, __shfl_xor_sync(0xffffffffu, mx0, 2));
            mx1 = fmaxf(mx1, __shfl_xor_sync(0xffffffffu, mx1, 1));
            mx1 = fmaxf(mx1, __shfl_xor_sync(0xffffffffu, mx1, 2));
            float mn0 = fmaxf(m0, mx0), mn1 = fmaxf(m1, mx1);
            float sc0 = __expf(m0 - mn0), sc1 = __expf(m1 - mn1);

            float rs0 = 0.f, rs1 = 0.f;
#pragma unroll
            for (int nt = 0; nt < 8; nt++) {
                float p0 = f2tff(__expf(s[nt][0] - mn0));
                float p1 = f2tff(__expf(s[nt][1] - mn0));
                float p2 = f2tff(__expf(s[nt][2] - mn1));
                float p3 = f2tff(__expf(s[nt][3] - mn1));
                rs0 += p0 + p1;
                rs1 += p2 + p3;
                *(float2*)&Ps[(rbase + g    ) * AST + nt * 8 + 2 * tg] = make_float2(p0, p1);
                *(float2*)&Ps[(rbase + g + 8) * AST + nt * 8 + 2 * tg] = make_float2(p2, p3);
            }
            rs0 += __shfl_xor_sync(0xffffffffu, rs0, 1);
            rs0 += __shfl_xor_sync(0xffffffffu, rs0, 2);
            rs1 += __shfl_xor_sync(0xffffffffu, rs1, 1);
            rs1 += __shfl_xor_sync(0xffffffffu, rs1, 2);
            l0 = l0 * sc0 + rs0;
            l1 = l1 * sc1 + rs1;
            m0 = mn0; m1 = mn1;
#pragma unroll
            for (int nt = 0; nt < 8; nt++) {
                o[nt][0] *= sc0; o[nt][1] *= sc0;
                o[nt][2] *= sc1; o[nt][3] *= sc1;
            }
            __syncwarp();

            // ---- O += P V (V consumed natural [t][d]) ----
#pragma unroll
            for (int ks = 0; ks < 8; ks++) {
                uint32_t a[4];
                a[0] = __float_as_uint(Ps[(rbase + g    ) * AST + ks * 8 + tg]);
                a[1] = __float_as_uint(Ps[(rbase + g + 8) * AST + ks * 8 + tg]);
                a[2] = __float_as_uint(Ps[(rbase + g    ) * AST + ks * 8 + tg + 4]);
                a[3] = __float_as_uint(Ps[(rbase + g + 8) * AST + ks * 8 + tg + 4]);
#pragma unroll
                for (int nt = 0; nt < 8; nt++) {
                    uint32_t bf[2];
                    bf[0] = __float_as_uint(Vd[(ks * 8 + tg    ) * AST + nt * 8 + g]);
                    bf[1] = __float_as_uint(Vd[(ks * 8 + tg + 4) * AST + nt * 8 + g]);
                    mma_tf32(o[nt], a, bf);
                }
            }
        }
        __syncthreads();
    }

    // Epilogue: normalize, write to g_A [B,S,E].
    const float inv0 = 1.0f / l0;
    const float inv1 = 1.0f / l1;
    const int row0 = q0 + rbase + g;
#pragma unroll
    for (int nt = 0; nt < 8; nt++) {
        int d = nt * 8 + 2 * tg;
        float* p0 = g_A + ((size_t)b * SS + row0    ) * EE + h * DKK + d;
        float* p1 = g_A + ((size_t)b * SS + row0 + 8) * EE + h * DKK + d;
        *(float2*)p0 = make_float2(o[nt][0] * inv0, o[nt][1] * inv0);
        *(float2*)p1 = make_float2(o[nt][2] * inv1, o[nt][3] * inv1);
    }
}

// ===========================================================================

extern "C" void kernel_launch(void* const* d_in, const int* in_sizes, int n_in,
                              void* d_out, int out_size)
{
    const float* x  = (const float*)d_in[0];
    const float* WQ = (const float*)d_in[1];
    const float* WK = (const float*)d_in[2];
    const float* WV = (const float*)d_in[3];
    const float* WO = (const float*)d_in[4];
    float* out = (float*)d_out;

    (void)in_sizes; (void)n_in; (void)out_size;

    // 0) Transpose + tf32-round weights into scratch.
    wtrans_kernel<<<dim3(EE / 32, EE / 32, 4), dim3(32, 8)>>>(WQ, WK, WV, WO);

    // 1) QKV projections (mma.sync tf32) into [B,H,S,dk] scratch.
    cudaFuncSetAttribute(gemm_tc<0>,
                         cudaFuncAttributeMaxDynamicSharedMemorySize,
                         GEMM_SMEM_BYTES);
    gemm_tc<0><<<dim3(EE / 128, MTOT / 128, 3), 256, GEMM_SMEM_BYTES>>>(x, nullptr);

    // 2) Causal flash attention (mma.sync tf32).
    cudaFuncSetAttribute(attn_tc,
                         cudaFuncAttributeMaxDynamicSharedMemorySize,
                         ATTN_SMEM_BYTES);
    attn_tc<<<dim3(SS / 128, HH, BB), 256, ATTN_SMEM_BYTES>>>();

    // 3) Output projection (mma.sync tf32).
    cudaFuncSetAttribute(gemm_tc<1>,
                         cudaFuncAttributeMaxDynamicSharedMemorySize,
                         GEMM_SMEM_BYTES);
    gemm_tc<1><<<dim3(EE / 128, MTOT / 128), 256, GEMM_SMEM_BYTES>>>(nullptr, out);
}

// round 5
// speedup vs baseline: 3.0415x; 1.1192x over previous
#include <cuda_runtime.h>
#include <cstdint>
#include <math.h>

#define BB   4
#define SS   2048
#define EE   1024
#define HH   16
#define DKK  64
#define MTOT (BB*SS)   // 8192

// Scratch (device globals; no allocation allowed)
__device__ float g_X[(size_t)MTOT*EE];            // tf32-rounded X
__device__ float g_Q[(size_t)BB*HH*SS*DKK];       // rounded at write
__device__ float g_K[(size_t)BB*HH*SS*DKK];
__device__ float g_V[(size_t)BB*HH*SS*DKK];
__device__ float g_A[(size_t)MTOT*EE];            // rounded at write
__device__ float g_WT[(size_t)4*EE*EE];           // transposed + rounded weights

// ===========================================================================
// helpers
// ===========================================================================

__device__ __forceinline__ uint32_t f2tf(float v) {
    uint32_t u;
    asm("cvt.rna.tf32.f32 %0, %1;" : "=r"(u) : "f"(v));
    return u;
}
__device__ __forceinline__ float f2tff(float v) {
    return __uint_as_float(f2tf(v));
}

__device__ __forceinline__ void mma_tf32(float* c, const uint32_t* a, const uint32_t* b) {
    asm volatile(
        "mma.sync.aligned.m16n8k8.row.col.f32.tf32.tf32.f32 "
        "{%0,%1,%2,%3}, {%4,%5,%6,%7}, {%8,%9}, {%0,%1,%2,%3};"
        : "+f"(c[0]), "+f"(c[1]), "+f"(c[2]), "+f"(c[3])
        : "r"(a[0]), "r"(a[1]), "r"(a[2]), "r"(a[3]), "r"(b[0]), "r"(b[1]));
}

__device__ __forceinline__ void ldsm_x4(uint32_t* r, uint32_t addr) {
    asm volatile("ldmatrix.sync.aligned.m8n8.x4.shared.b16 {%0,%1,%2,%3}, [%4];"
                 : "=r"(r[0]), "=r"(r[1]), "=r"(r[2]), "=r"(r[3]) : "r"(addr));
}

__device__ __forceinline__ uint32_t smem_u32(const void* p) {
    uint32_t a;
    asm("{ .reg .u64 t; cvta.to.shared.u64 t, %1; cvt.u32.u64 %0, t; }"
        : "=r"(a) : "l"(p));
    return a;
}

__device__ __forceinline__ void cp16(uint32_t dst, const float* src) {
    asm volatile("cp.async.cg.shared.global [%0], [%1], 16;"
                 :: "r"(dst), "l"(src) : "memory");
}
#define CP_COMMIT() asm volatile("cp.async.commit_group;" ::: "memory")
#define CP_WAIT(N)  asm volatile("cp.async.wait_group %0;" :: "n"(N) : "memory")

// ===========================================================================
// Prepass: round X to tf32.
// ===========================================================================
__global__ __launch_bounds__(256) void xround_kernel(const float* __restrict__ X)
{
    size_t i = ((size_t)blockIdx.x * 256 + threadIdx.x) * 4;
    float4 v = *(const float4*)(X + i);
    *(float4*)(g_X + i) = make_float4(f2tff(v.x), f2tff(v.y), f2tff(v.z), f2tff(v.w));
}

// Weight transpose + round: g_WT[w][n][k] = rna(W_w[k][n])
__global__ __launch_bounds__(256) void wtrans_kernel(
    const float* __restrict__ WQ, const float* __restrict__ WK,
    const float* __restrict__ WV, const float* __restrict__ WO)
{
    __shared__ float t[32][33];
    const int w = blockIdx.z;
    const float* W = (w == 0) ? WQ : (w == 1) ? WK : (w == 2) ? WV : WO;
    float* O = g_WT + (size_t)w * EE * EE;
    const int n0 = blockIdx.x * 32;
    const int k0 = blockIdx.y * 32;
    const int tx = threadIdx.x, ty = threadIdx.y;

#pragma unroll
    for (int i = ty; i < 32; i += 8)
        t[i][tx] = W[(size_t)(k0 + i) * EE + n0 + tx];
    __syncthreads();
#pragma unroll
    for (int i = ty; i < 32; i += 8)
        O[(size_t)(n0 + i) * EE + k0 + tx] = f2tff(t[tx][i]);
}

// ===========================================================================
// tf32 GEMM v2: 128x128 tile, 256 thr, cp.async 3-stage, ldmatrix fragments.
// Stage: A[128][36] + B[128][36] floats (strides 144B: 16B-aligned,
// ldmatrix-conflict-free). 3 stages = 110592 B.
// MODE 0: A=g_X, B=W{Q,K,V}, out=g_{Q,K,V} [B,H,S,dk], ROUNDED at write.
// MODE 1: A=g_A, B=WO, out=d_out [M,E], raw.
// ===========================================================================
#define GSTAGE  36864                       // bytes per stage (A+B)
#define GEMM_SMEM_BYTES (3 * GSTAGE)        // 110592

template <int MODE>
__global__ __launch_bounds__(256, 2) void gemm_tc(float* __restrict__ OutP)
{
    extern __shared__ float smf[];
    const uint32_t sb = smem_u32(smf);
    const int tid  = threadIdx.x;
    const int lane = tid & 31;
    const int w    = tid >> 5;
    const int g    = lane >> 2;
    const int tg   = lane & 3;
    const int wm   = w & 3;
    const int wn   = w >> 2;
    const int m0   = blockIdx.y * 128;
    const int n0   = blockIdx.x * 128;

    const float* Ag = MODE ? g_A : g_X;
    const float* Bt = g_WT + (size_t)(MODE ? 3 : blockIdx.z) * EE * EE;
    float* outp;
    if (MODE) outp = OutP;
    else outp = (blockIdx.z == 0) ? g_Q : (blockIdx.z == 1) ? g_K : g_V;

    // cp.async thread mapping: f = tid + i*256; r=f>>3 (0..127), c=f&7.
    const int cr = tid >> 3;
    const int cc = tid & 7;

    // ldmatrix per-thread invariant offsets (bytes).
    const uint32_t aoff = (uint32_t)(lane & 15) * 144u + ((lane >> 4) & 1) * 16u;
    const uint32_t boff = (uint32_t)((lane & 7) + ((lane & 16) >> 1)) * 144u
                        + ((lane & 8) >> 3) * 16u;

    auto issue = [&](int s) {
        const uint32_t ab = sb + (uint32_t)(s % 3) * GSTAGE;
        const uint32_t bb = ab + 18432u;
        const int k0 = s * 32;
#pragma unroll
        for (int i = 0; i < 4; i++) {
            int r = cr + i * 32;
            cp16(ab + (uint32_t)r * 144u + cc * 16u,
                 Ag + (size_t)(m0 + r) * EE + k0 + cc * 4);
            cp16(bb + (uint32_t)r * 144u + cc * 16u,
                 Bt + (size_t)(n0 + r) * EE + k0 + cc * 4);
        }
    };

    float c[2][8][4];
#pragma unroll
    for (int mt = 0; mt < 2; mt++)
#pragma unroll
        for (int nt = 0; nt < 8; nt++)
#pragma unroll
            for (int i = 0; i < 4; i++) c[mt][nt][i] = 0.f;

    issue(0); CP_COMMIT();
    issue(1); CP_COMMIT();

    for (int j = 0; j < 32; j++) {
        __syncthreads();                 // compute(j-1) done -> buffer (j+2)%3 free
        if (j + 2 < 32) issue(j + 2);
        CP_COMMIT();                     // always commit (uniform group accounting)
        CP_WAIT(2);                      // stage j complete
        __syncthreads();

        const uint32_t ab = sb + (uint32_t)(j % 3) * GSTAGE;
        const uint32_t bb = ab + 18432u;
#pragma unroll
        for (int ks = 0; ks < 4; ks++) {
            uint32_t a[2][4], bq[4][4];
            ldsm_x4(a[0], ab + (uint32_t)(wm * 32     ) * 144u + ks * 32u + aoff);
            ldsm_x4(a[1], ab + (uint32_t)(wm * 32 + 16) * 144u + ks * 32u + aoff);
#pragma unroll
            for (int p = 0; p < 4; p++)
                ldsm_x4(bq[p], bb + (uint32_t)(wn * 64 + p * 16) * 144u + ks * 32u + boff);
#pragma unroll
            for (int mt = 0; mt < 2; mt++)
#pragma unroll
                for (int nt = 0; nt < 8; nt++)
                    mma_tf32(c[mt][nt], a[mt], &bq[nt >> 1][(nt & 1) * 2]);
        }
    }

#pragma unroll
    for (int mt = 0; mt < 2; mt++) {
#pragma unroll
        for (int nt = 0; nt < 8; nt++) {
            int row = m0 + wm * 32 + mt * 16 + g;
            int col = n0 + wn * 64 + nt * 8 + 2 * tg;
            if (MODE) {
                float* o0 = outp + (size_t)row * EE + col;
                float* o1 = outp + (size_t)(row + 8) * EE + col;
                *(float2*)o0 = make_float2(c[mt][nt][0], c[mt][nt][1]);
                *(float2*)o1 = make_float2(c[mt][nt][2], c[mt][nt][3]);
            } else {
                int bidx = row >> 11;
                int s    = row & (SS - 1);
                int h    = col >> 6;
                int d    = col & 63;
                float* o0 = outp + (((size_t)(bidx * HH + h) * SS + s    ) * DKK + d);
                float* o1 = outp + (((size_t)(bidx * HH + h) * SS + s + 8) * DKK + d);
                *(float2*)o0 = make_float2(f2tff(c[mt][nt][0]), f2tff(c[mt][nt][1]));
                *(float2*)o1 = make_float2(f2tff(c[mt][nt][2]), f2tff(c[mt][nt][3]));
            }
        }
    }
}

// ===========================================================================
// Causal flash attention (mma.sync tf32, ldmatrix fragments, cp.async KV).
// CTA = 128 q-rows of one (b,h); 8 warps x 16 rows; KV chunk 64, 2 buffers.
// Strides 68 floats (272B: 16B-aligned, ldmatrix conflict-free).
// ===========================================================================
#define AST 68
#define ASTB 272u
#define AKV (64 * AST)                    // floats per KV buffer
#define ATTN_SMEM_FLOATS (128*AST + 2*AKV + 2*AKV + 128*AST)
#define ATTN_SMEM_BYTES  (ATTN_SMEM_FLOATS * 4)   // 139264

__global__ __launch_bounds__(256) void attn_tc()
{
    extern __shared__ float sm[];
    float* Qs = sm;                        // [128][68]
    float* Ks = sm + 128 * AST;            // [2][64][68]
    float* Vs = Ks + 2 * AKV;              // [2][64][68]
    float* Ps = Vs + 2 * AKV;              // [128][68]
    const uint32_t sb    = smem_u32(sm);
    const uint32_t Qb    = sb;
    const uint32_t Kb    = sb + 128 * ASTB;
    const uint32_t Vb    = Kb + 2 * 64 * ASTB;
    const uint32_t Pb    = Vb + 2 * 64 * ASTB;

    const int tid  = threadIdx.x;
    const int lane = tid & 31;
    const int w    = tid >> 5;
    const int g    = lane >> 2;
    const int tg   = lane & 3;

    const int qblk = gridDim.x - 1 - blockIdx.x;   // heavy CTAs first
    const int q0   = qblk * 128;
    const int h    = blockIdx.y;
    const int b    = blockIdx.z;
    const size_t base = ((size_t)(b * HH + h) * SS) * DKK;

    // ldmatrix invariant offsets (bytes), stride 272.
    const uint32_t aoff = (uint32_t)(lane & 15) * ASTB + ((lane >> 4) & 1) * 16u;
    const uint32_t boff = (uint32_t)((lane & 7) + ((lane & 16) >> 1)) * ASTB
                        + ((lane & 8) >> 3) * 16u;

    // cp.async mapping for 64x64 tiles: f = tid + i*256; r=f>>4, c=f&15.
    const int cr = tid >> 4;
    const int cc = tid & 15;

    auto issue_kv = [&](int j) {
        const uint32_t kd = Kb + (uint32_t)(j & 1) * 64 * ASTB;
        const uint32_t vd = Vb + (uint32_t)(j & 1) * 64 * ASTB;
        const int t0 = j * 64;
#pragma unroll
        for (int i = 0; i < 4; i++) {
            int r = cr + i * 16;
            cp16(kd + (uint32_t)r * ASTB + cc * 16u,
                 g_K + base + (size_t)(t0 + r) * DKK + cc * 4);
            cp16(vd + (uint32_t)r * ASTB + cc * 16u,
                 g_V + base + (size_t)(t0 + r) * DKK + cc * 4);
        }
    };

    // Stage Q (pre-rounded), 128x64.
#pragma unroll
    for (int i = 0; i < 8; i++) {
        int f = tid + i * 256;
        int r = f >> 4, c4 = f & 15;
        float4 v = *(const float4*)(g_Q + base + (size_t)(q0 + r) * DKK + c4 * 4);
        *(float4*)(Qs + r * AST + c4 * 4) = v;
    }

    float o[8][4];
#pragma unroll
    for (int nt = 0; nt < 8; nt++)
#pragma unroll
        for (int i = 0; i < 4; i++) o[nt][i] = 0.f;
    float m0 = -1e30f, m1 = -1e30f, l0 = 0.f, l1 = 0.f;

    const int nch   = 2 * qblk + 2;
    const int rbase = w * 16;
    const int grow0 = q0 + rbase + g;

    issue_kv(0); CP_COMMIT();

    for (int j = 0; j < nch; j++) {
        __syncthreads();                 // compute(j-1) done -> buffer (j+1)&1 free
        if (j + 1 < nch) issue_kv(j + 1);
        CP_COMMIT();
        CP_WAIT(1);                      // stage j complete
        __syncthreads();

        const uint32_t kdb = Kb + (uint32_t)(j & 1) * 64 * ASTB;
        const float*   Vd  = Vs + (j & 1) * AKV;

        const int t0 = j * 64;
        if (t0 <= q0 + rbase + 15) {
            // ---- S = Q K^T ----
            float s[8][4];
#pragma unroll
            for (int nt = 0; nt < 8; nt++)
#pragma unroll
                for (int i = 0; i < 4; i++) s[nt][i] = 0.f;

#pragma unroll
            for (int ks = 0; ks < 8; ks++) {
                uint32_t a[4], bq[4][4];
                ldsm_x4(a, Qb + (uint32_t)rbase * ASTB + ks * 32u + aoff);
#pragma unroll
                for (int p = 0; p < 4; p++)
                    ldsm_x4(bq[p], kdb + (uint32_t)(p * 16) * ASTB + ks * 32u + boff);
#pragma unroll
                for (int nt = 0; nt < 8; nt++)
                    mma_tf32(s[nt], a, &bq[nt >> 1][(nt & 1) * 2]);
            }

            // ---- scale + causal mask ----
#pragma unroll
            for (int nt = 0; nt < 8; nt++) {
                int c0 = t0 + nt * 8 + 2 * tg;
                int c1 = c0 + 1;
                s[nt][0] = (c0 <= grow0    ) ? s[nt][0] * 0.125f : -1e30f;
                s[nt][1] = (c1 <= grow0    ) ? s[nt][1] * 0.125f : -1e30f;
                s[nt][2] = (c0 <= grow0 + 8) ? s[nt][2] * 0.125f : -1e30f;
                s[nt][3] = (c1 <= grow0 + 8) ? s[nt][3] * 0.125f : -1e30f;
            }

            // ---- online softmax ----
            float mx0 = -1e30f, mx1 = -1e30f;
#pragma unroll
            for (int nt = 0; nt < 8; nt++) {
                mx0 = fmaxf(mx0, fmaxf(s[nt][0], s[nt][1]));
                mx1 = fmaxf(mx1, fmaxf(s[nt][2], s[nt][3]));
            }
            mx0 = fmaxf(mx0, __shfl_xor_sync(0xffffffffu, mx0, 1));
            mx0 = fmaxf(mx0, __shfl_xor_sync(0xffffffffu, mx0, 2));
            mx1 = fmaxf(mx1, __shfl_xor_sync(0xffffffffu, mx1, 1));
            mx1 = fmaxf(mx1, __shfl_xor_sync(0xffffffffu, mx1, 2));
            float mn0 = fmaxf(m0, mx0), mn1 = fmaxf(m1, mx1);
            float sc0 = __expf(m0 - mn0), sc1 = __expf(m1 - mn1);

            float rs0 = 0.f, rs1 = 0.f;
#pragma unroll
            for (int nt = 0; nt < 8; nt++) {
                float p0 = f2tff(__expf(s[nt][0] - mn0));
                float p1 = f2tff(__expf(s[nt][1] - mn0));
                float p2 = f2tff(__expf(s[nt][2] - mn1));
                float p3 = f2tff(__expf(s[nt][3] - mn1));
                rs0 += p0 + p1;
                rs1 += p2 + p3;
                *(float2*)&Ps[(rbase + g    ) * AST + nt * 8 + 2 * tg] = make_float2(p0, p1);
                *(float2*)&Ps[(rbase + g + 8) * AST + nt * 8 + 2 * tg] = make_float2(p2, p3);
            }
            rs0 += __shfl_xor_sync(0xffffffffu, rs0, 1);
            rs0 += __shfl_xor_sync(0xffffffffu, rs0, 2);
            rs1 += __shfl_xor_sync(0xffffffffu, rs1, 1);
            rs1 += __shfl_xor_sync(0xffffffffu, rs1, 2);
            l0 = l0 * sc0 + rs0;
            l1 = l1 * sc1 + rs1;
            m0 = mn0; m1 = mn1;
#pragma unroll
            for (int nt = 0; nt < 8; nt++) {
                o[nt][0] *= sc0; o[nt][1] *= sc0;
                o[nt][2] *= sc1; o[nt][3] *= sc1;
            }
            __syncwarp();

            // ---- O += P V ----
#pragma unroll
            for (int ks = 0; ks < 8; ks++) {
                uint32_t a[4];
                ldsm_x4(a, Pb + (uint32_t)rbase * ASTB + ks * 32u + aoff);
#pragma unroll
                for (int nt = 0; nt < 8; nt++) {
                    uint32_t bf[2];
                    bf[0] = __float_as_uint(Vd[(ks * 8 + tg    ) * AST + nt * 8 + g]);
                    bf[1] = __float_as_uint(Vd[(ks * 8 + tg + 4) * AST + nt * 8 + g]);
                    mma_tf32(o[nt], a, bf);
                }
            }
        }
    }

    // Epilogue: normalize, round, write g_A [B,S,E].
    const float inv0 = 1.0f / l0;
    const float inv1 = 1.0f / l1;
    const int row0 = q0 + rbase + g;
#pragma unroll
    for (int nt = 0; nt < 8; nt++) {
        int d = nt * 8 + 2 * tg;
        float* p0 = g_A + ((size_t)b * SS + row0    ) * EE + h * DKK + d;
        float* p1 = g_A + ((size_t)b * SS + row0 + 8) * EE + h * DKK + d;
        *(float2*)p0 = make_float2(f2tff(o[nt][0] * inv0), f2tff(o[nt][1] * inv0));
        *(float2*)p1 = make_float2(f2tff(o[nt][2] * inv1), f2tff(o[nt][3] * inv1));
    }
}

// ===========================================================================

extern "C" void kernel_launch(void* const* d_in, const int* in_sizes, int n_in,
                              void* d_out, int out_size)
{
    const float* x  = (const float*)d_in[0];
    const float* WQ = (const float*)d_in[1];
    const float* WK = (const float*)d_in[2];
    const float* WV = (const float*)d_in[3];
    const float* WO = (const float*)d_in[4];
    float* out = (float*)d_out;

    (void)in_sizes; (void)n_in; (void)out_size;

    // 0) Round X; transpose+round weights.
    xround_kernel<<<(MTOT * EE) / (256 * 4), 256>>>(x);
    wtrans_kernel<<<dim3(EE / 32, EE / 32, 4), dim3(32, 8)>>>(WQ, WK, WV, WO);

    // 1) QKV projections.
    cudaFuncSetAttribute(gemm_tc<0>,
                         cudaFuncAttributeMaxDynamicSharedMemorySize,
                         GEMM_SMEM_BYTES);
    gemm_tc<0><<<dim3(EE / 128, MTOT / 128, 3), 256, GEMM_SMEM_BYTES>>>(nullptr);

    // 2) Causal flash attention.
    cudaFuncSetAttribute(attn_tc,
                         cudaFuncAttributeMaxDynamicSharedMemorySize,
                         ATTN_SMEM_BYTES);
    attn_tc<<<dim3(SS / 128, HH, BB), 256, ATTN_SMEM_BYTES>>>();

    // 3) Output projection.
    cudaFuncSetAttribute(gemm_tc<1>,
                         cudaFuncAttributeMaxDynamicSharedMemorySize,
                         GEMM_SMEM_BYTES);
    gemm_tc<1><<<dim3(EE / 128, MTOT / 128), 256, GEMM_SMEM_BYTES>>>(out);
}

// round 6
// speedup vs baseline: 3.0441x; 1.0008x over previous
#include <cuda_runtime.h>
#include <cstdint>
#include <math.h>

#define BB   4
#define SS   2048
#define EE   1024
#define HH   16
#define DKK  64
#define MTOT (BB*SS)   // 8192

// Scratch (device globals; no allocation allowed)
__device__ float g_X[(size_t)MTOT*EE];            // tf32-rounded X
__device__ float g_Q[(size_t)BB*HH*SS*DKK];       // rounded at write
__device__ float g_K[(size_t)BB*HH*SS*DKK];
__device__ float g_V[(size_t)BB*HH*SS*DKK];
__device__ float g_A[(size_t)MTOT*EE];            // rounded at write
__device__ float g_WT[(size_t)4*EE*EE];           // transposed + rounded weights

// ===========================================================================
// helpers
// ===========================================================================

__device__ __forceinline__ uint32_t f2tf(float v) {
    uint32_t u;
    asm("cvt.rna.tf32.f32 %0, %1;" : "=r"(u) : "f"(v));
    return u;
}
__device__ __forceinline__ float f2tff(float v) {
    return __uint_as_float(f2tf(v));
}

__device__ __forceinline__ void mma_tf32(float* c, const uint32_t* a, const uint32_t* b) {
    asm volatile(
        "mma.sync.aligned.m16n8k8.row.col.f32.tf32.tf32.f32 "
        "{%0,%1,%2,%3}, {%4,%5,%6,%7}, {%8,%9}, {%0,%1,%2,%3};"
        : "+f"(c[0]), "+f"(c[1]), "+f"(c[2]), "+f"(c[3])
        : "r"(a[0]), "r"(a[1]), "r"(a[2]), "r"(a[3]), "r"(b[0]), "r"(b[1]));
}

__device__ __forceinline__ void ldsm_x4(uint32_t* r, uint32_t addr) {
    asm volatile("ldmatrix.sync.aligned.m8n8.x4.shared.b16 {%0,%1,%2,%3}, [%4];"
                 : "=r"(r[0]), "=r"(r[1]), "=r"(r[2]), "=r"(r[3]) : "r"(addr));
}

__device__ __forceinline__ uint32_t smem_u32(const void* p) {
    uint32_t a;
    asm("{ .reg .u64 t; cvta.to.shared.u64 t, %1; cvt.u32.u64 %0, t; }"
        : "=r"(a) : "l"(p));
    return a;
}

__device__ __forceinline__ void cp16(uint32_t dst, const float* src) {
    asm volatile("cp.async.cg.shared.global [%0], [%1], 16;"
                 :: "r"(dst), "l"(src) : "memory");
}
#define CP_COMMIT() asm volatile("cp.async.commit_group;" ::: "memory")
#define CP_WAIT(N)  asm volatile("cp.async.wait_group %0;" :: "n"(N) : "memory")

// ===========================================================================
// Prepass: round X to tf32.
// ===========================================================================
__global__ __launch_bounds__(256) void xround_kernel(const float* __restrict__ X)
{
    size_t i = ((size_t)blockIdx.x * 256 + threadIdx.x) * 4;
    float4 v = *(const float4*)(X + i);
    *(float4*)(g_X + i) = make_float4(f2tff(v.x), f2tff(v.y), f2tff(v.z), f2tff(v.w));
}

// Weight transpose + round: g_WT[w][n][k] = rna(W_w[k][n])
__global__ __launch_bounds__(256) void wtrans_kernel(
    const float* __restrict__ WQ, const float* __restrict__ WK,
    const float* __restrict__ WV, const float* __restrict__ WO)
{
    __shared__ float t[32][33];
    const int w = blockIdx.z;
    const float* W = (w == 0) ? WQ : (w == 1) ? WK : (w == 2) ? WV : WO;
    float* O = g_WT + (size_t)w * EE * EE;
    const int n0 = blockIdx.x * 32;
    const int k0 = blockIdx.y * 32;
    const int tx = threadIdx.x, ty = threadIdx.y;

#pragma unroll
    for (int i = ty; i < 32; i += 8)
        t[i][tx] = W[(size_t)(k0 + i) * EE + n0 + tx];
    __syncthreads();
#pragma unroll
    for (int i = ty; i < 32; i += 8)
        O[(size_t)(n0 + i) * EE + k0 + tx] = f2tff(t[tx][i]);
}

// ===========================================================================
// tf32 GEMM (unchanged from R5): 128x128 tile, 256 thr, cp.async 3-stage,
// ldmatrix fragments.
// ===========================================================================
#define GSTAGE  36864
#define GEMM_SMEM_BYTES (3 * GSTAGE)        // 110592

template <int MODE>
__global__ __launch_bounds__(256, 2) void gemm_tc(float* __restrict__ OutP)
{
    extern __shared__ float smf[];
    const uint32_t sb = smem_u32(smf);
    const int tid  = threadIdx.x;
    const int lane = tid & 31;
    const int w    = tid >> 5;
    const int g    = lane >> 2;
    const int tg   = lane & 3;
    const int wm   = w & 3;
    const int wn   = w >> 2;
    const int m0   = blockIdx.y * 128;
    const int n0   = blockIdx.x * 128;

    const float* Ag = MODE ? g_A : g_X;
    const float* Bt = g_WT + (size_t)(MODE ? 3 : blockIdx.z) * EE * EE;
    float* outp;
    if (MODE) outp = OutP;
    else outp = (blockIdx.z == 0) ? g_Q : (blockIdx.z == 1) ? g_K : g_V;

    const int cr = tid >> 3;
    const int cc = tid & 7;

    const uint32_t aoff = (uint32_t)(lane & 15) * 144u + ((lane >> 4) & 1) * 16u;
    const uint32_t boff = (uint32_t)((lane & 7) + ((lane & 16) >> 1)) * 144u
                        + ((lane & 8) >> 3) * 16u;

    auto issue = [&](int s) {
        const uint32_t ab = sb + (uint32_t)(s % 3) * GSTAGE;
        const uint32_t bb = ab + 18432u;
        const int k0 = s * 32;
#pragma unroll
        for (int i = 0; i < 4; i++) {
            int r = cr + i * 32;
            cp16(ab + (uint32_t)r * 144u + cc * 16u,
                 Ag + (size_t)(m0 + r) * EE + k0 + cc * 4);
            cp16(bb + (uint32_t)r * 144u + cc * 16u,
                 Bt + (size_t)(n0 + r) * EE + k0 + cc * 4);
        }
    };

    float c[2][8][4];
#pragma unroll
    for (int mt = 0; mt < 2; mt++)
#pragma unroll
        for (int nt = 0; nt < 8; nt++)
#pragma unroll
            for (int i = 0; i < 4; i++) c[mt][nt][i] = 0.f;

    issue(0); CP_COMMIT();
    issue(1); CP_COMMIT();

    for (int j = 0; j < 32; j++) {
        __syncthreads();
        if (j + 2 < 32) issue(j + 2);
        CP_COMMIT();
        CP_WAIT(2);
        __syncthreads();

        const uint32_t ab = sb + (uint32_t)(j % 3) * GSTAGE;
        const uint32_t bb = ab + 18432u;
#pragma unroll
        for (int ks = 0; ks < 4; ks++) {
            uint32_t a[2][4], bq[4][4];
            ldsm_x4(a[0], ab + (uint32_t)(wm * 32     ) * 144u + ks * 32u + aoff);
            ldsm_x4(a[1], ab + (uint32_t)(wm * 32 + 16) * 144u + ks * 32u + aoff);
#pragma unroll
            for (int p = 0; p < 4; p++)
                ldsm_x4(bq[p], bb + (uint32_t)(wn * 64 + p * 16) * 144u + ks * 32u + boff);
#pragma unroll
            for (int mt = 0; mt < 2; mt++)
#pragma unroll
                for (int nt = 0; nt < 8; nt++)
                    mma_tf32(c[mt][nt], a[mt], &bq[nt >> 1][(nt & 1) * 2]);
        }
    }

#pragma unroll
    for (int mt = 0; mt < 2; mt++) {
#pragma unroll
        for (int nt = 0; nt < 8; nt++) {
            int row = m0 + wm * 32 + mt * 16 + g;
            int col = n0 + wn * 64 + nt * 8 + 2 * tg;
            if (MODE) {
                float* o0 = outp + (size_t)row * EE + col;
                float* o1 = outp + (size_t)(row + 8) * EE + col;
                *(float2*)o0 = make_float2(c[mt][nt][0], c[mt][nt][1]);
                *(float2*)o1 = make_float2(c[mt][nt][2], c[mt][nt][3]);
            } else {
                int bidx = row >> 11;
                int s    = row & (SS - 1);
                int h    = col >> 6;
                int d    = col & 63;
                float* o0 = outp + (((size_t)(bidx * HH + h) * SS + s    ) * DKK + d);
                float* o1 = outp + (((size_t)(bidx * HH + h) * SS + s + 8) * DKK + d);
                *(float2*)o0 = make_float2(f2tff(c[mt][nt][0]), f2tff(c[mt][nt][1]));
                *(float2*)o1 = make_float2(f2tff(c[mt][nt][2]), f2tff(c[mt][nt][3]));
            }
        }
    }
}

// ===========================================================================
// Causal flash attention v3: CTA = 256 q-rows, 16 warps (512 thr).
// K double-buffered, V single-buffered (separate cp.async commit groups:
// PV wait never blocks on next chunk's K). SMEM 191.5KB -> 16 warps/SM.
// ===========================================================================
#define AST 68
#define ASTB 272u
#define AKV (64 * AST)
#define AQROWS 256
#define ATTN_SMEM_FLOATS (AQROWS*AST + 2*AKV + AKV + AQROWS*AST)
#define ATTN_SMEM_BYTES  (ATTN_SMEM_FLOATS * 4)   // 191488

__global__ __launch_bounds__(512, 1) void attn_tc()
{
    extern __shared__ float sm[];
    float* Qs = sm;                          // [256][68]
    float* Vs = sm + AQROWS * AST + 2 * AKV; // [64][68] (single)
    float* Ps = Vs + AKV;                    // [256][68]
    const uint32_t sb = smem_u32(sm);
    const uint32_t Qb = sb;
    const uint32_t Kb = sb + AQROWS * ASTB;
    const uint32_t Vbuf = Kb + 2 * 64 * ASTB;
    const uint32_t Pb = Vbuf + 64 * ASTB;

    const int tid  = threadIdx.x;
    const int lane = tid & 31;
    const int w    = tid >> 5;               // 0..15
    const int g    = lane >> 2;
    const int tg   = lane & 3;

    const int qblk = gridDim.x - 1 - blockIdx.x;   // heavy CTAs first
    const int q0   = qblk * AQROWS;
    const int h    = blockIdx.y;
    const int b    = blockIdx.z;
    const size_t base = ((size_t)(b * HH + h) * SS) * DKK;

    const uint32_t aoff = (uint32_t)(lane & 15) * ASTB + ((lane >> 4) & 1) * 16u;
    const uint32_t boff = (uint32_t)((lane & 7) + ((lane & 16) >> 1)) * ASTB
                        + ((lane & 8) >> 3) * 16u;

    // cp.async mapping for 64x64 tiles with 512 threads: 2 rows each.
    const int cr = tid >> 4;                  // 0..31
    const int cc = tid & 15;

    auto issue_K = [&](int j) {
        const uint32_t kd = Kb + (uint32_t)(j & 1) * 64 * ASTB;
        const int t0 = j * 64;
#pragma unroll
        for (int i = 0; i < 2; i++) {
            int r = cr + i * 32;
            cp16(kd + (uint32_t)r * ASTB + cc * 16u,
                 g_K + base + (size_t)(t0 + r) * DKK + cc * 4);
        }
    };
    auto issue_V = [&](int j) {
        const int t0 = j * 64;
#pragma unroll
        for (int i = 0; i < 2; i++) {
            int r = cr + i * 32;
            cp16(Vbuf + (uint32_t)r * ASTB + cc * 16u,
                 g_V + base + (size_t)(t0 + r) * DKK + cc * 4);
        }
    };

    // Stage Q (pre-rounded), 256x64.
#pragma unroll
    for (int i = 0; i < 8; i++) {
        int f = tid + i * 512;
        int r = f >> 4, c4 = f & 15;
        float4 v = *(const float4*)(g_Q + base + (size_t)(q0 + r) * DKK + c4 * 4);
        *(float4*)(Qs + r * AST + c4 * 4) = v;
    }

    float o[8][4];
#pragma unroll
    for (int nt = 0; nt < 8; nt++)
#pragma unroll
        for (int i = 0; i < 4; i++) o[nt][i] = 0.f;
    float m0 = -1e30f, m1 = -1e30f, l0 = 0.f, l1 = 0.f;

    const int nch   = 4 * qblk + 4;
    const int rbase = w * 16;
    const int grow0 = q0 + rbase + g;

    issue_K(0); CP_COMMIT();

    for (int j = 0; j < nch; j++) {
        __syncthreads();                 // Vbuf free (PV j-1 done); Kbuf[(j+1)&1] free
        issue_V(j);  CP_COMMIT();        // group V_j
        if (j + 1 < nch) issue_K(j + 1);
        CP_COMMIT();                     // group K_{j+1} (may be empty)
        CP_WAIT(2);                      // K_j complete (V_j, K_{j+1} may fly)
        __syncthreads();

        const uint32_t kdb = Kb + (uint32_t)(j & 1) * 64 * ASTB;
        const int t0 = j * 64;
        const bool active = (t0 <= q0 + rbase + 15);

        float s[8][4];
        if (active) {
            // ---- S = Q K^T ----
#pragma unroll
            for (int nt = 0; nt < 8; nt++)
#pragma unroll
                for (int i = 0; i < 4; i++) s[nt][i] = 0.f;

#pragma unroll
            for (int ks = 0; ks < 8; ks++) {
                uint32_t a[4], bq[4][4];
                ldsm_x4(a, Qb + (uint32_t)rbase * ASTB + ks * 32u + aoff);
#pragma unroll
                for (int p = 0; p < 4; p++)
                    ldsm_x4(bq[p], kdb + (uint32_t)(p * 16) * ASTB + ks * 32u + boff);
#pragma unroll
                for (int nt = 0; nt < 8; nt++)
                    mma_tf32(s[nt], a, &bq[nt >> 1][(nt & 1) * 2]);
            }

            // ---- scale + causal mask ----
#pragma unroll
            for (int nt = 0; nt < 8; nt++) {
                int c0 = t0 + nt * 8 + 2 * tg;
                int c1 = c0 + 1;
                s[nt][0] = (c0 <= grow0    ) ? s[nt][0] * 0.125f : -1e30f;
                s[nt][1] = (c1 <= grow0    ) ? s[nt][1] * 0.125f : -1e30f;
                s[nt][2] = (c0 <= grow0 + 8) ? s[nt][2] * 0.125f : -1e30f;
                s[nt][3] = (c1 <= grow0 + 8) ? s[nt][3] * 0.125f : -1e30f;
            }

            // ---- online softmax ----
            float mx0 = -1e30f, mx1 = -1e30f;
#pragma unroll
            for (int nt = 0; nt < 8; nt++) {
                mx0 = fmaxf(mx0, fmaxf(s[nt][0], s[nt][1]));
                mx1 = fmaxf(mx1, fmaxf(s[nt][2], s[nt][3]));
            }
            mx0 = fmaxf(mx0, __shfl_xor_sync(0xffffffffu, mx0, 1));
            mx0 = fmaxf(mx0, __shfl_xor_sync(0xffffffffu, mx0, 2));
            mx1 = fmaxf(mx1, __shfl_xor_sync(0xffffffffu, mx1, 1));
            mx1 = fmaxf(mx1, __shfl_xor_sync(0xffffffffu, mx1, 2));
            float mn0 = fmaxf(m0, mx0), mn1 = fmaxf(m1, mx1);
            float sc0 = __expf(m0 - mn0), sc1 = __expf(m1 - mn1);

            float rs0 = 0.f, rs1 = 0.f;
#pragma unroll
            for (int nt = 0; nt < 8; nt++) {
                float p0 = f2tff(__expf(s[nt][0] - mn0));
                float p1 = f2tff(__expf(s[nt][1] - mn0));
                float p2 = f2tff(__expf(s[nt][2] - mn1));
                float p3 = f2tff(__expf(s[nt][3] - mn1));
                rs0 += p0 + p1;
                rs1 += p2 + p3;
                *(float2*)&Ps[(rbase + g    ) * AST + nt * 8 + 2 * tg] = make_float2(p0, p1);
                *(float2*)&Ps[(rbase + g + 8) * AST + nt * 8 + 2 * tg] = make_float2(p2, p3);
            }
            rs0 += __shfl_xor_sync(0xffffffffu, rs0, 1);
            rs0 += __shfl_xor_sync(0xffffffffu, rs0, 2);
            rs1 += __shfl_xor_sync(0xffffffffu, rs1, 1);
            rs1 += __shfl_xor_sync(0xffffffffu, rs1, 2);
            l0 = l0 * sc0 + rs0;
            l1 = l1 * sc1 + rs1;
            m0 = mn0; m1 = mn1;
#pragma unroll
            for (int nt = 0; nt < 8; nt++) {
                o[nt][0] *= sc0; o[nt][1] *= sc0;
                o[nt][2] *= sc1; o[nt][3] *= sc1;
            }
        }

        CP_WAIT(1);                      // V_j complete (K_{j+1} may fly)
        __syncthreads();

        if (active) {
            // ---- O += P V ----
#pragma unroll
            for (int ks = 0; ks < 8; ks++) {
                uint32_t a[4];
                ldsm_x4(a, Pb + (uint32_t)rbase * ASTB + ks * 32u + aoff);
#pragma unroll
                for (int nt = 0; nt < 8; nt++) {
                    uint32_t bf[2];
                    bf[0] = __float_as_uint(Vs[(ks * 8 + tg    ) * AST + nt * 8 + g]);
                    bf[1] = __float_as_uint(Vs[(ks * 8 + tg + 4) * AST + nt * 8 + g]);
                    mma_tf32(o[nt], a, bf);
                }
            }
        }
    }

    // Epilogue: normalize, round, write g_A [B,S,E].
    const float inv0 = 1.0f / l0;
    const float inv1 = 1.0f / l1;
    const int row0 = q0 + rbase + g;
#pragma unroll
    for (int nt = 0; nt < 8; nt++) {
        int d = nt * 8 + 2 * tg;
        float* p0 = g_A + ((size_t)b * SS + row0    ) * EE + h * DKK + d;
        float* p1 = g_A + ((size_t)b * SS + row0 + 8) * EE + h * DKK + d;
        *(float2*)p0 = make_float2(f2tff(o[nt][0] * inv0), f2tff(o[nt][1] * inv0));
        *(float2*)p1 = make_float2(f2tff(o[nt][2] * inv1), f2tff(o[nt][3] * inv1));
    }
}

// ===========================================================================

extern "C" void kernel_launch(void* const* d_in, const int* in_sizes, int n_in,
                              void* d_out, int out_size)
{
    const float* x  = (const float*)d_in[0];
    const float* WQ = (const float*)d_in[1];
    const float* WK = (const float*)d_in[2];
    const float* WV = (const float*)d_in[3];
    const float* WO = (const float*)d_in[4];
    float* out = (float*)d_out;

    (void)in_sizes; (void)n_in; (void)out_size;

    // 0) Round X; transpose+round weights.
    xround_kernel<<<(MTOT * EE) / (256 * 4), 256>>>(x);
    wtrans_kernel<<<dim3(EE / 32, EE / 32, 4), dim3(32, 8)>>>(WQ, WK, WV, WO);

    // 1) QKV projections.
    cudaFuncSetAttribute(gemm_tc<0>,
                         cudaFuncAttributeMaxDynamicSharedMemorySize,
                         GEMM_SMEM_BYTES);
    gemm_tc<0><<<dim3(EE / 128, MTOT / 128, 3), 256, GEMM_SMEM_BYTES>>>(nullptr);

    // 2) Causal flash attention (256 q-rows / 16 warps per CTA).
    cudaFuncSetAttribute(attn_tc,
                         cudaFuncAttributeMaxDynamicSharedMemorySize,
                         ATTN_SMEM_BYTES);
    attn_tc<<<dim3(SS / AQROWS, HH, BB), 512, ATTN_SMEM_BYTES>>>();

    // 3) Output projection.
    cudaFuncSetAttribute(gemm_tc<1>,
                         cudaFuncAttributeMaxDynamicSharedMemorySize,
                         GEMM_SMEM_BYTES);
    gemm_tc<1><<<dim3(EE / 128, MTOT / 128), 256, GEMM_SMEM_BYTES>>>(out);
}

// round 7
// speedup vs baseline: 3.1257x; 1.0268x over previous
#include <cuda_runtime.h>
#include <cstdint>
#include <math.h>

#define BB   4
#define SS   2048
#define EE   1024
#define HH   16
#define DKK  64
#define MTOT (BB*SS)   // 8192

// Scratch (device globals; no allocation allowed)
__device__ float g_X[(size_t)MTOT*EE];            // tf32-rounded X
__device__ float g_Q[(size_t)BB*HH*SS*DKK];       // rounded at write
__device__ float g_K[(size_t)BB*HH*SS*DKK];
__device__ float g_V[(size_t)BB*HH*SS*DKK];
__device__ float g_A[(size_t)MTOT*EE];            // rounded at write
__device__ float g_WT[(size_t)4*EE*EE];           // transposed + rounded weights

// ===========================================================================
// helpers
// ===========================================================================

__device__ __forceinline__ uint32_t f2tf(float v) {
    uint32_t u;
    asm("cvt.rna.tf32.f32 %0, %1;" : "=r"(u) : "f"(v));
    return u;
}
__device__ __forceinline__ float f2tff(float v) {
    return __uint_as_float(f2tf(v));
}

__device__ __forceinline__ void mma_tf32(float* c, const uint32_t* a, const uint32_t* b) {
    asm volatile(
        "mma.sync.aligned.m16n8k8.row.col.f32.tf32.tf32.f32 "
        "{%0,%1,%2,%3}, {%4,%5,%6,%7}, {%8,%9}, {%0,%1,%2,%3};"
        : "+f"(c[0]), "+f"(c[1]), "+f"(c[2]), "+f"(c[3])
        : "r"(a[0]), "r"(a[1]), "r"(a[2]), "r"(a[3]), "r"(b[0]), "r"(b[1]));
}

__device__ __forceinline__ void ldsm_x4(uint32_t* r, uint32_t addr) {
    asm volatile("ldmatrix.sync.aligned.m8n8.x4.shared.b16 {%0,%1,%2,%3}, [%4];"
                 : "=r"(r[0]), "=r"(r[1]), "=r"(r[2]), "=r"(r[3]) : "r"(addr));
}

__device__ __forceinline__ uint32_t smem_u32(const void* p) {
    uint32_t a;
    asm("{ .reg .u64 t; cvta.to.shared.u64 t, %1; cvt.u32.u64 %0, t; }"
        : "=r"(a) : "l"(p));
    return a;
}

__device__ __forceinline__ void cp16(uint32_t dst, const float* src) {
    asm volatile("cp.async.cg.shared.global [%0], [%1], 16;"
                 :: "r"(dst), "l"(src) : "memory");
}
#define CP_COMMIT() asm volatile("cp.async.commit_group;" ::: "memory")
#define CP_WAIT(N)  asm volatile("cp.async.wait_group %0;" :: "n"(N) : "memory")

// ===========================================================================
// Prepass: round X to tf32.
// ===========================================================================
__global__ __launch_bounds__(256) void xround_kernel(const float* __restrict__ X)
{
    size_t i = ((size_t)blockIdx.x * 256 + threadIdx.x) * 4;
    float4 v = *(const float4*)(X + i);
    *(float4*)(g_X + i) = make_float4(f2tff(v.x), f2tff(v.y), f2tff(v.z), f2tff(v.w));
}

// Weight transpose + round: g_WT[w][n][k] = rna(W_w[k][n])
__global__ __launch_bounds__(256) void wtrans_kernel(
    const float* __restrict__ WQ, const float* __restrict__ WK,
    const float* __restrict__ WV, const float* __restrict__ WO)
{
    __shared__ float t[32][33];
    const int w = blockIdx.z;
    const float* W = (w == 0) ? WQ : (w == 1) ? WK : (w == 2) ? WV : WO;
    float* O = g_WT + (size_t)w * EE * EE;
    const int n0 = blockIdx.x * 32;
    const int k0 = blockIdx.y * 32;
    const int tx = threadIdx.x, ty = threadIdx.y;

#pragma unroll
    for (int i = ty; i < 32; i += 8)
        t[i][tx] = W[(size_t)(k0 + i) * EE + n0 + tx];
    __syncthreads();
#pragma unroll
    for (int i = ty; i < 32; i += 8)
        O[(size_t)(n0 + i) * EE + k0 + tx] = f2tff(t[tx][i]);
}

// ===========================================================================
// tf32 GEMM (unchanged): 128x128 tile, 256 thr, cp.async 3-stage, ldmatrix.
// ===========================================================================
#define GSTAGE  36864
#define GEMM_SMEM_BYTES (3 * GSTAGE)        // 110592

template <int MODE>
__global__ __launch_bounds__(256, 2) void gemm_tc(float* __restrict__ OutP)
{
    extern __shared__ float smf[];
    const uint32_t sb = smem_u32(smf);
    const int tid  = threadIdx.x;
    const int lane = tid & 31;
    const int w    = tid >> 5;
    const int g    = lane >> 2;
    const int tg   = lane & 3;
    const int wm   = w & 3;
    const int wn   = w >> 2;
    const int m0   = blockIdx.y * 128;
    const int n0   = blockIdx.x * 128;

    const float* Ag = MODE ? g_A : g_X;
    const float* Bt = g_WT + (size_t)(MODE ? 3 : blockIdx.z) * EE * EE;
    float* outp;
    if (MODE) outp = OutP;
    else outp = (blockIdx.z == 0) ? g_Q : (blockIdx.z == 1) ? g_K : g_V;

    const int cr = tid >> 3;
    const int cc = tid & 7;

    const uint32_t aoff = (uint32_t)(lane & 15) * 144u + ((lane >> 4) & 1) * 16u;
    const uint32_t boff = (uint32_t)((lane & 7) + ((lane & 16) >> 1)) * 144u
                        + ((lane & 8) >> 3) * 16u;

    auto issue = [&](int s) {
        const uint32_t ab = sb + (uint32_t)(s % 3) * GSTAGE;
        const uint32_t bb = ab + 18432u;
        const int k0 = s * 32;
#pragma unroll
        for (int i = 0; i < 4; i++) {
            int r = cr + i * 32;
            cp16(ab + (uint32_t)r * 144u + cc * 16u,
                 Ag + (size_t)(m0 + r) * EE + k0 + cc * 4);
            cp16(bb + (uint32_t)r * 144u + cc * 16u,
                 Bt + (size_t)(n0 + r) * EE + k0 + cc * 4);
        }
    };

    float c[2][8][4];
#pragma unroll
    for (int mt = 0; mt < 2; mt++)
#pragma unroll
        for (int nt = 0; nt < 8; nt++)
#pragma unroll
            for (int i = 0; i < 4; i++) c[mt][nt][i] = 0.f;

    issue(0); CP_COMMIT();
    issue(1); CP_COMMIT();

    for (int j = 0; j < 32; j++) {
        __syncthreads();
        if (j + 2 < 32) issue(j + 2);
        CP_COMMIT();
        CP_WAIT(2);
        __syncthreads();

        const uint32_t ab = sb + (uint32_t)(j % 3) * GSTAGE;
        const uint32_t bb = ab + 18432u;
#pragma unroll
        for (int ks = 0; ks < 4; ks++) {
            uint32_t a[2][4], bq[4][4];
            ldsm_x4(a[0], ab + (uint32_t)(wm * 32     ) * 144u + ks * 32u + aoff);
            ldsm_x4(a[1], ab + (uint32_t)(wm * 32 + 16) * 144u + ks * 32u + aoff);
#pragma unroll
            for (int p = 0; p < 4; p++)
                ldsm_x4(bq[p], bb + (uint32_t)(wn * 64 + p * 16) * 144u + ks * 32u + boff);
#pragma unroll
            for (int mt = 0; mt < 2; mt++)
#pragma unroll
                for (int nt = 0; nt < 8; nt++)
                    mma_tf32(c[mt][nt], a[mt], &bq[nt >> 1][(nt & 1) * 2]);
        }
    }

#pragma unroll
    for (int mt = 0; mt < 2; mt++) {
#pragma unroll
        for (int nt = 0; nt < 8; nt++) {
            int row = m0 + wm * 32 + mt * 16 + g;
            int col = n0 + wn * 64 + nt * 8 + 2 * tg;
            if (MODE) {
                float* o0 = outp + (size_t)row * EE + col;
                float* o1 = outp + (size_t)(row + 8) * EE + col;
                *(float2*)o0 = make_float2(c[mt][nt][0], c[mt][nt][1]);
                *(float2*)o1 = make_float2(c[mt][nt][2], c[mt][nt][3]);
            } else {
                int bidx = row >> 11;
                int s    = row & (SS - 1);
                int h    = col >> 6;
                int d    = col & 63;
                float* o0 = outp + (((size_t)(bidx * HH + h) * SS + s    ) * DKK + d);
                float* o1 = outp + (((size_t)(bidx * HH + h) * SS + s + 8) * DKK + d);
                *(float2*)o0 = make_float2(f2tff(c[mt][nt][0]), f2tff(c[mt][nt][1]));
                *(float2*)o1 = make_float2(f2tff(c[mt][nt][2]), f2tff(c[mt][nt][3]));
            }
        }
    }
}

// ===========================================================================
// Causal flash attention v4: CTA = 256 q-rows, 16 warps (512 thr).
// K double-buffered via cp.async; V loaded by LDG at loop-top and stored
// TRANSPOSED (Vt[d][t]) so PV B-fragments use ldmatrix (no scalar LDS).
// ===========================================================================
#define AST 68
#define ASTB 272u
#define AKV (64 * AST)
#define AQROWS 256
#define ATTN_SMEM_FLOATS (AQROWS*AST + 2*AKV + AKV + AQROWS*AST)
#define ATTN_SMEM_BYTES  (ATTN_SMEM_FLOATS * 4)   // 191488

__global__ __launch_bounds__(512, 1) void attn_tc()
{
    extern __shared__ float sm[];
    float* Qs = sm;                          // [256][68]
    float* Vt = sm + AQROWS * AST + 2 * AKV; // [64][68]  Vt[d][t]
    float* Ps = Vt + AKV;                    // [256][68]
    const uint32_t sb   = smem_u32(sm);
    const uint32_t Qb   = sb;
    const uint32_t Kb   = sb + AQROWS * ASTB;
    const uint32_t Vtb  = Kb + 2 * 64 * ASTB;
    const uint32_t Pb   = Vtb + 64 * ASTB;

    const int tid  = threadIdx.x;
    const int lane = tid & 31;
    const int w    = tid >> 5;               // 0..15
    const int g    = lane >> 2;
    const int tg   = lane & 3;

    const int qblk = gridDim.x - 1 - blockIdx.x;   // heavy CTAs first
    const int q0   = qblk * AQROWS;
    const int h    = blockIdx.y;
    const int b    = blockIdx.z;
    const size_t base = ((size_t)(b * HH + h) * SS) * DKK;

    const uint32_t aoff = (uint32_t)(lane & 15) * ASTB + ((lane >> 4) & 1) * 16u;
    const uint32_t boff = (uint32_t)((lane & 7) + ((lane & 16) >> 1)) * ASTB
                        + ((lane & 8) >> 3) * 16u;

    // cp.async K mapping (64x64 tile, 512 threads -> 2 rows each).
    const int cr = tid >> 4;                  // 0..31
    const int cc = tid & 15;

    // V transpose mapping: thread covers V[vt][vd0..vd0+7].
    const int vt  = tid & 63;                 // t within chunk (lane-distinct)
    const int vd0 = (tid >> 6) << 3;          // d0: 0,8,...,56

    auto issue_K = [&](int j) {
        const uint32_t kd = Kb + (uint32_t)(j & 1) * 64 * ASTB;
        const int t0 = j * 64;
#pragma unroll
        for (int i = 0; i < 2; i++) {
            int r = cr + i * 32;
            cp16(kd + (uint32_t)r * ASTB + cc * 16u,
                 g_K + base + (size_t)(t0 + r) * DKK + cc * 4);
        }
    };

    // Stage Q (pre-rounded), 256x64.
#pragma unroll
    for (int i = 0; i < 8; i++) {
        int f = tid + i * 512;
        int r = f >> 4, c4 = f & 15;
        float4 v = *(const float4*)(g_Q + base + (size_t)(q0 + r) * DKK + c4 * 4);
        *(float4*)(Qs + r * AST + c4 * 4) = v;
    }

    float o[8][4];
#pragma unroll
    for (int nt = 0; nt < 8; nt++)
#pragma unroll
        for (int i = 0; i < 4; i++) o[nt][i] = 0.f;
    float m0 = -1e30f, m1 = -1e30f, l0 = 0.f, l1 = 0.f;

    const int nch   = 4 * qblk + 4;
    const int rbase = w * 16;
    const int grow0 = q0 + rbase + g;

    issue_K(0); CP_COMMIT();

    for (int j = 0; j < nch; j++) {
        __syncthreads();                 // Vt free (PV j-1 done); K[(j+1)&1] free

        // V_j global loads (registers; consumed after softmax).
        const int t0 = j * 64;
        float4 rv0 = *(const float4*)(g_V + base + (size_t)(t0 + vt) * DKK + vd0);
        float4 rv1 = *(const float4*)(g_V + base + (size_t)(t0 + vt) * DKK + vd0 + 4);

        if (j + 1 < nch) issue_K(j + 1);
        CP_COMMIT();                     // group K_{j+1} (may be empty)
        CP_WAIT(1);                      // K_j complete
        __syncthreads();

        const uint32_t kdb = Kb + (uint32_t)(j & 1) * 64 * ASTB;
        const bool active = (t0 <= q0 + rbase + 15);

        if (active) {
            // ---- S = Q K^T ----
            float s[8][4];
#pragma unroll
            for (int nt = 0; nt < 8; nt++)
#pragma unroll
                for (int i = 0; i < 4; i++) s[nt][i] = 0.f;

#pragma unroll
            for (int ks = 0; ks < 8; ks++) {
                uint32_t a[4], bq[4][4];
                ldsm_x4(a, Qb + (uint32_t)rbase * ASTB + ks * 32u + aoff);
#pragma unroll
                for (int p = 0; p < 4; p++)
                    ldsm_x4(bq[p], kdb + (uint32_t)(p * 16) * ASTB + ks * 32u + boff);
#pragma unroll
                for (int nt = 0; nt < 8; nt++)
                    mma_tf32(s[nt], a, &bq[nt >> 1][(nt & 1) * 2]);
            }

            // ---- scale + causal mask ----
#pragma unroll
            for (int nt = 0; nt < 8; nt++) {
                int c0 = t0 + nt * 8 + 2 * tg;
                int c1 = c0 + 1;
                s[nt][0] = (c0 <= grow0    ) ? s[nt][0] * 0.125f : -1e30f;
                s[nt][1] = (c1 <= grow0    ) ? s[nt][1] * 0.125f : -1e30f;
                s[nt][2] = (c0 <= grow0 + 8) ? s[nt][2] * 0.125f : -1e30f;
                s[nt][3] = (c1 <= grow0 + 8) ? s[nt][3] * 0.125f : -1e30f;
            }

            // ---- online softmax ----
            float mx0 = -1e30f, mx1 = -1e30f;
#pragma unroll
            for (int nt = 0; nt < 8; nt++) {
                mx0 = fmaxf(mx0, fmaxf(s[nt][0], s[nt][1]));
                mx1 = fmaxf(mx1, fmaxf(s[nt][2], s[nt][3]));
            }
            mx0 = fmaxf(mx0, __shfl_xor_sync(0xffffffffu, mx0, 1));
            mx0 = fmaxf(mx0, __shfl_xor_sync(0xffffffffu, mx0, 2));
            mx1 = fmaxf(mx1, __shfl_xor_sync(0xffffffffu, mx1, 1));
            mx1 = fmaxf(mx1, __shfl_xor_sync(0xffffffffu, mx1, 2));
            float mn0 = fmaxf(m0, mx0), mn1 = fmaxf(m1, mx1);
            float sc0 = __expf(m0 - mn0), sc1 = __expf(m1 - mn1);

            float rs0 = 0.f, rs1 = 0.f;
#pragma unroll
            for (int nt = 0; nt < 8; nt++) {
                float p0 = f2tff(__expf(s[nt][0] - mn0));
                float p1 = f2tff(__expf(s[nt][1] - mn0));
                float p2 = f2tff(__expf(s[nt][2] - mn1));
                float p3 = f2tff(__expf(s[nt][3] - mn1));
                rs0 += p0 + p1;
                rs1 += p2 + p3;
                *(float2*)&Ps[(rbase + g    ) * AST + nt * 8 + 2 * tg] = make_float2(p0, p1);
                *(float2*)&Ps[(rbase + g + 8) * AST + nt * 8 + 2 * tg] = make_float2(p2, p3);
            }
            rs0 += __shfl_xor_sync(0xffffffffu, rs0, 1);
            rs0 += __shfl_xor_sync(0xffffffffu, rs0, 2);
            rs1 += __shfl_xor_sync(0xffffffffu, rs1, 1);
            rs1 += __shfl_xor_sync(0xffffffffu, rs1, 2);
            l0 = l0 * sc0 + rs0;
            l1 = l1 * sc1 + rs1;
            m0 = mn0; m1 = mn1;
#pragma unroll
            for (int nt = 0; nt < 8; nt++) {
                o[nt][0] *= sc0; o[nt][1] *= sc0;
                o[nt][2] *= sc1; o[nt][3] *= sc1;
            }
        }

        // ---- V transpose: Vt[d][t] = V[t][d] (bank-conflict-free STS) ----
        {
            float* col = Vt + vt;
            col[(vd0 + 0) * AST] = rv0.x;
            col[(vd0 + 1) * AST] = rv0.y;
            col[(vd0 + 2) * AST] = rv0.z;
            col[(vd0 + 3) * AST] = rv0.w;
            col[(vd0 + 4) * AST] = rv1.x;
            col[(vd0 + 5) * AST] = rv1.y;
            col[(vd0 + 6) * AST] = rv1.z;
            col[(vd0 + 7) * AST] = rv1.w;
        }
        __syncthreads();                 // Vt ready

        if (active) {
            // ---- O += P V (B-fragments via ldmatrix from Vt) ----
#pragma unroll
            for (int ks = 0; ks < 8; ks++) {
                uint32_t a[4], bv[4][4];
                ldsm_x4(a, Pb + (uint32_t)rbase * ASTB + ks * 32u + aoff);
#pragma unroll
                for (int p = 0; p < 4; p++)
                    ldsm_x4(bv[p], Vtb + (uint32_t)(p * 16) * ASTB + ks * 32u + boff);
#pragma unroll
                for (int nt = 0; nt < 8; nt++)
                    mma_tf32(o[nt], a, &bv[nt >> 1][(nt & 1) * 2]);
            }
        }
    }

    // Epilogue: normalize, round, write g_A [B,S,E].
    const float inv0 = 1.0f / l0;
    const float inv1 = 1.0f / l1;
    const int row0 = q0 + rbase + g;
#pragma unroll
    for (int nt = 0; nt < 8; nt++) {
        int d = nt * 8 + 2 * tg;
        float* p0 = g_A + ((size_t)b * SS + row0    ) * EE + h * DKK + d;
        float* p1 = g_A + ((size_t)b * SS + row0 + 8) * EE + h * DKK + d;
        *(float2*)p0 = make_float2(f2tff(o[nt][0] * inv0), f2tff(o[nt][1] * inv0));
        *(float2*)p1 = make_float2(f2tff(o[nt][2] * inv1), f2tff(o[nt][3] * inv1));
    }
}

// ===========================================================================

extern "C" void kernel_launch(void* const* d_in, const int* in_sizes, int n_in,
                              void* d_out, int out_size)
{
    const float* x  = (const float*)d_in[0];
    const float* WQ = (const float*)d_in[1];
    const float* WK = (const float*)d_in[2];
    const float* WV = (const float*)d_in[3];
    const float* WO = (const float*)d_in[4];
    float* out = (float*)d_out;

    (void)in_sizes; (void)n_in; (void)out_size;

    // 0) Round X; transpose+round weights.
    xround_kernel<<<(MTOT * EE) / (256 * 4), 256>>>(x);
    wtrans_kernel<<<dim3(EE / 32, EE / 32, 4), dim3(32, 8)>>>(WQ, WK, WV, WO);

    // 1) QKV projections.
    cudaFuncSetAttribute(gemm_tc<0>,
                         cudaFuncAttributeMaxDynamicSharedMemorySize,
                         GEMM_SMEM_BYTES);
    gemm_tc<0><<<dim3(EE / 128, MTOT / 128, 3), 256, GEMM_SMEM_BYTES>>>(nullptr);

    // 2) Causal flash attention.
    cudaFuncSetAttribute(attn_tc,
                         cudaFuncAttributeMaxDynamicSharedMemorySize,
                         ATTN_SMEM_BYTES);
    attn_tc<<<dim3(SS / AQROWS, HH, BB), 512, ATTN_SMEM_BYTES>>>();

    // 3) Output projection.
    cudaFuncSetAttribute(gemm_tc<1>,
                         cudaFuncAttributeMaxDynamicSharedMemorySize,
                         GEMM_SMEM_BYTES);
    gemm_tc<1><<<dim3(EE / 128, MTOT / 128), 256, GEMM_SMEM_BYTES>>>(out);
}